// round 4
// baseline (speedup 1.0000x reference)
#include <cuda_runtime.h>
#include <math.h>

// Problem constants
#define Bb   2
#define Ls   2048
#define Dd   1024
#define Hh   16
#define DHd  64
#define FFd  4096
#define Mrows (Bb*Ls)      // 4096
#define LD    (Ls*Dd)      // 2097152
#define NPART 64

// ---------------- scratch (static device globals; no allocation) -------------
__device__ float g_h[Mrows*Dd];
__device__ float g_q[Mrows*Dd];
__device__ float g_k[Mrows*Dd];
__device__ float g_v[Mrows*Dd];
__device__ float g_o[Mrows*Dd];
__device__ float g_r1[Mrows*Dd];
__device__ float g_y[Mrows*Dd];
__device__ float g_f[Mrows*FFd];
__device__ float g_part[Bb*NPART*2];
__device__ float g_stats[Bb*2];

// ---------------- LayerNorm over (L,D) jointly per batch ---------------------
__global__ void ln_partial(const float* __restrict__ x) {
    const int b = blockIdx.y;
    const int tid = threadIdx.x;
    const int chunk4 = (LD / NPART) / 4;            // 8192 float4 per block
    const float4* xp = (const float4*)(x + (size_t)b * LD) + (size_t)blockIdx.x * chunk4;
    float s = 0.f, s2 = 0.f;
    for (int i = tid; i < chunk4; i += 256) {
        float4 v = xp[i];
        s  += v.x + v.y + v.z + v.w;
        s2 += v.x*v.x + v.y*v.y + v.z*v.z + v.w*v.w;
    }
    __shared__ float sh[2][256];
    sh[0][tid] = s; sh[1][tid] = s2;
    __syncthreads();
    for (int st = 128; st > 0; st >>= 1) {
        if (tid < st) { sh[0][tid] += sh[0][tid+st]; sh[1][tid] += sh[1][tid+st]; }
        __syncthreads();
    }
    if (tid == 0) {
        g_part[(b*NPART + blockIdx.x)*2 + 0] = sh[0][0];
        g_part[(b*NPART + blockIdx.x)*2 + 1] = sh[1][0];
    }
}

__global__ void ln_final() {
    const int b = blockIdx.x, t = threadIdx.x;   // 32 threads
    float s  = g_part[(b*NPART + t)*2 + 0] + g_part[(b*NPART + t + 32)*2 + 0];
    float s2 = g_part[(b*NPART + t)*2 + 1] + g_part[(b*NPART + t + 32)*2 + 1];
    for (int o = 16; o; o >>= 1) {
        s  += __shfl_xor_sync(0xffffffffu, s,  o);
        s2 += __shfl_xor_sync(0xffffffffu, s2, o);
    }
    if (t == 0) {
        float mu  = s / (float)LD;
        float var = s2 / (float)LD - mu*mu;
        g_stats[b*2 + 0] = mu;
        g_stats[b*2 + 1] = rsqrtf(var + 1e-5f);
    }
}

__global__ void ln_apply(const float* __restrict__ in, float* __restrict__ out) {
    const int idx = blockIdx.x * blockDim.x + threadIdx.x;   // float4 index
    const int b = idx / (LD/4);
    const float mu = g_stats[b*2 + 0], rs = g_stats[b*2 + 1];
    float4 v = ((const float4*)in)[idx];
    v.x = (v.x - mu) * rs; v.y = (v.y - mu) * rs;
    v.z = (v.z - mu) * rs; v.w = (v.w - mu) * rs;
    ((float4*)out)[idx] = v;
}

// ---------------- FP32 GEMM: C[M,N] = A[M,K] * W[N,K]^T + bias (+res)(relu) --
template<bool RELU, bool RESID>
__global__ __launch_bounds__(256, 2)
void gemm_tn(const float* __restrict__ A, const float* __restrict__ W,
             const float* __restrict__ bias, const float* __restrict__ R,
             float* __restrict__ C, int Ndim, int Kdim)
{
    __shared__ float As[8][128];
    __shared__ float Ws[8][128];
    const int bm = blockIdx.y * 128, bn = blockIdx.x * 128;
    const int tid = threadIdx.x;
    const int lr = tid >> 1;            // 0..127
    const int lk = (tid & 1) * 4;       // 0 or 4
    const float* Ap = A + (size_t)(bm + lr) * Kdim + lk;
    const float* Wp = W + (size_t)(bn + lr) * Kdim + lk;
    const int ry = (tid >> 4) * 4;      // 0..60
    const int cx = (tid & 15) * 4;      // 0..60

    float acc[8][8];
    #pragma unroll
    for (int i = 0; i < 8; i++)
        #pragma unroll
        for (int j = 0; j < 8; j++) acc[i][j] = 0.f;

    for (int k0 = 0; k0 < Kdim; k0 += 8) {
        float4 av = *(const float4*)(Ap + k0);
        float4 wv = *(const float4*)(Wp + k0);
        As[lk+0][lr] = av.x; As[lk+1][lr] = av.y; As[lk+2][lr] = av.z; As[lk+3][lr] = av.w;
        Ws[lk+0][lr] = wv.x; Ws[lk+1][lr] = wv.y; Ws[lk+2][lr] = wv.z; Ws[lk+3][lr] = wv.w;
        __syncthreads();
        #pragma unroll
        for (int k = 0; k < 8; k++) {
            float4 a0 = *(const float4*)&As[k][ry];
            float4 a1 = *(const float4*)&As[k][64 + ry];
            float4 b0 = *(const float4*)&Ws[k][cx];
            float4 b1 = *(const float4*)&Ws[k][64 + cx];
            float a[8] = {a0.x,a0.y,a0.z,a0.w,a1.x,a1.y,a1.z,a1.w};
            float bb[8] = {b0.x,b0.y,b0.z,b0.w,b1.x,b1.y,b1.z,b1.w};
            #pragma unroll
            for (int i = 0; i < 8; i++)
                #pragma unroll
                for (int j = 0; j < 8; j++)
                    acc[i][j] += a[i] * bb[j];
        }
        __syncthreads();
    }

    #pragma unroll
    for (int i = 0; i < 8; i++) {
        const int r = bm + ((i < 4) ? (ry + i) : (64 + ry + i - 4));
        #pragma unroll
        for (int j = 0; j < 8; j++) {
            const int c = bn + ((j < 4) ? (cx + j) : (64 + cx + j - 4));
            float v = acc[i][j] + bias[c];
            if (RESID) v += R[(size_t)r * Ndim + c];
            if (RELU)  v = fmaxf(v, 0.f);
            C[(size_t)r * Ndim + c] = v;
        }
    }
}

// ---------------- Flash attention: per (b, head, 64-row q tile) --------------
// scale = 1/sqrt(H) = 0.25 (faithful to the source bug)
__global__ __launch_bounds__(256)
void attn_kernel(const float* __restrict__ q, const float* __restrict__ k,
                 const float* __restrict__ v, float* __restrict__ o)
{
    __shared__ float Qs[64][68];
    __shared__ float Ks[32][68];
    __shared__ float Vs[32][68];
    __shared__ float Ss[64][33];

    const int b = blockIdx.z, hh = blockIdx.y, q0 = blockIdx.x * 64;
    const int tid = threadIdx.x;

    // load Q tile: 64 rows x 64 cols
    {
        const int r = tid >> 2, cb = (tid & 3) * 16;
        const float* src = q + ((size_t)(b*Ls + q0 + r) * Dd) + hh*DHd + cb;
        #pragma unroll
        for (int i = 0; i < 16; i += 4) {
            float4 t = *(const float4*)(src + i);
            Qs[r][cb+i] = t.x; Qs[r][cb+i+1] = t.y; Qs[r][cb+i+2] = t.z; Qs[r][cb+i+3] = t.w;
        }
    }

    const int row = tid >> 2;        // softmax/PV mapping: 4 threads per row
    const int cg  = tid & 3;
    float m = -1e30f, l = 0.f;
    float4 a0 = {0,0,0,0}, a1 = {0,0,0,0}, a2 = {0,0,0,0}, a3 = {0,0,0,0};

    __syncthreads();

    for (int t0 = 0; t0 < Ls; t0 += 32) {
        // load K,V chunk: 32 rows x 64 cols each
        {
            const int r = tid >> 3, cb = (tid & 7) * 8;
            const float* ks = k + ((size_t)(b*Ls + t0 + r) * Dd) + hh*DHd + cb;
            const float* vs = v + ((size_t)(b*Ls + t0 + r) * Dd) + hh*DHd + cb;
            float4 t1 = *(const float4*)ks, t2 = *(const float4*)(ks + 4);
            Ks[r][cb+0]=t1.x; Ks[r][cb+1]=t1.y; Ks[r][cb+2]=t1.z; Ks[r][cb+3]=t1.w;
            Ks[r][cb+4]=t2.x; Ks[r][cb+5]=t2.y; Ks[r][cb+6]=t2.z; Ks[r][cb+7]=t2.w;
            float4 t3 = *(const float4*)vs, t4 = *(const float4*)(vs + 4);
            Vs[r][cb+0]=t3.x; Vs[r][cb+1]=t3.y; Vs[r][cb+2]=t3.z; Vs[r][cb+3]=t3.w;
            Vs[r][cb+4]=t4.x; Vs[r][cb+5]=t4.y; Vs[r][cb+6]=t4.z; Vs[r][cb+7]=t4.w;
        }
        __syncthreads();

        // S = Q @ K^T (2 rows x 4 cols per thread), scaled by 0.25
        {
            const int sr = (tid >> 3) * 2;   // rows sr, sr+1
            const int sc = tid & 7;          // cols sc + 8*j
            float s0[4] = {0,0,0,0}, s1[4] = {0,0,0,0};
            #pragma unroll
            for (int d = 0; d < 64; d += 4) {
                float4 qa = *(const float4*)&Qs[sr][d];
                float4 qb = *(const float4*)&Qs[sr+1][d];
                #pragma unroll
                for (int j = 0; j < 4; j++) {
                    float4 kv = *(const float4*)&Ks[sc + 8*j][d];
                    s0[j] += qa.x*kv.x + qa.y*kv.y + qa.z*kv.z + qa.w*kv.w;
                    s1[j] += qb.x*kv.x + qb.y*kv.y + qb.z*kv.z + qb.w*kv.w;
                }
            }
            #pragma unroll
            for (int j = 0; j < 4; j++) {
                Ss[sr  ][sc + 8*j] = s0[j] * 0.25f;
                Ss[sr+1][sc + 8*j] = s1[j] * 0.25f;
            }
        }
        __syncthreads();

        // online softmax update (4 threads per row, 8 cols each)
        float pv[8], pm = -1e30f;
        #pragma unroll
        for (int j = 0; j < 8; j++) { pv[j] = Ss[row][cg*8 + j]; pm = fmaxf(pm, pv[j]); }
        pm = fmaxf(pm, __shfl_xor_sync(0xffffffffu, pm, 1));
        pm = fmaxf(pm, __shfl_xor_sync(0xffffffffu, pm, 2));
        const float nm = fmaxf(m, pm);
        const float corr = __expf(m - nm);
        float ps = 0.f;
        #pragma unroll
        for (int j = 0; j < 8; j++) {
            pv[j] = __expf(pv[j] - nm);
            ps += pv[j];
            Ss[row][cg*8 + j] = pv[j];
        }
        ps += __shfl_xor_sync(0xffffffffu, ps, 1);
        ps += __shfl_xor_sync(0xffffffffu, ps, 2);
        l = l * corr + ps;
        m = nm;
        a0.x*=corr; a0.y*=corr; a0.z*=corr; a0.w*=corr;
        a1.x*=corr; a1.y*=corr; a1.z*=corr; a1.w*=corr;
        a2.x*=corr; a2.y*=corr; a2.z*=corr; a2.w*=corr;
        a3.x*=corr; a3.y*=corr; a3.z*=corr; a3.w*=corr;
        __syncwarp();

        // acc += P @ V   (each thread owns 16 d-columns: cg*16 .. +16)
        #pragma unroll
        for (int kk = 0; kk < 32; kk++) {
            const float p = Ss[row][kk];
            const float4* vr = (const float4*)&Vs[kk][cg*16];
            float4 v0 = vr[0], v1 = vr[1], v2 = vr[2], v3 = vr[3];
            a0.x += p*v0.x; a0.y += p*v0.y; a0.z += p*v0.z; a0.w += p*v0.w;
            a1.x += p*v1.x; a1.y += p*v1.y; a1.z += p*v1.z; a1.w += p*v1.w;
            a2.x += p*v2.x; a2.y += p*v2.y; a2.z += p*v2.z; a2.w += p*v2.w;
            a3.x += p*v3.x; a3.y += p*v3.y; a3.z += p*v3.z; a3.w += p*v3.w;
        }
        __syncthreads();
    }

    const float inv = 1.f / l;
    float* dst = o + ((size_t)(b*Ls + q0 + row) * Dd) + hh*DHd + cg*16;
    float4 w0 = {a0.x*inv, a0.y*inv, a0.z*inv, a0.w*inv};
    float4 w1 = {a1.x*inv, a1.y*inv, a1.z*inv, a1.w*inv};
    float4 w2 = {a2.x*inv, a2.y*inv, a2.z*inv, a2.w*inv};
    float4 w3 = {a3.x*inv, a3.y*inv, a3.z*inv, a3.w*inv};
    ((float4*)dst)[0] = w0; ((float4*)dst)[1] = w1;
    ((float4*)dst)[2] = w2; ((float4*)dst)[3] = w3;
}

// ---------------- host orchestration ----------------------------------------
extern "C" void kernel_launch(void* const* d_in, const int* in_sizes, int n_in,
                              void* d_out, int out_size)
{
    (void)in_sizes; (void)n_in; (void)out_size;
    const float* x  = (const float*)d_in[0];
    const float* wq = (const float*)d_in[1];
    const float* bq = (const float*)d_in[2];
    const float* wk = (const float*)d_in[3];
    const float* bk = (const float*)d_in[4];
    const float* wv = (const float*)d_in[5];
    const float* bv = (const float*)d_in[6];
    const float* wo = (const float*)d_in[7];
    const float* bo = (const float*)d_in[8];
    const float* w1 = (const float*)d_in[9];
    const float* b1 = (const float*)d_in[10];
    const float* w2 = (const float*)d_in[11];
    const float* b2 = (const float*)d_in[12];
    float* out = (float*)d_out;

    float *h, *q, *k, *v, *o, *r1, *y, *f;
    cudaGetSymbolAddress((void**)&h,  g_h);
    cudaGetSymbolAddress((void**)&q,  g_q);
    cudaGetSymbolAddress((void**)&k,  g_k);
    cudaGetSymbolAddress((void**)&v,  g_v);
    cudaGetSymbolAddress((void**)&o,  g_o);
    cudaGetSymbolAddress((void**)&r1, g_r1);
    cudaGetSymbolAddress((void**)&y,  g_y);
    cudaGetSymbolAddress((void**)&f,  g_f);

    const dim3 gProj(Dd/128, Mrows/128);     // (8, 32)
    const dim3 gFF1(FFd/128, Mrows/128);     // (32, 32)

    // LN1
    ln_partial<<<dim3(NPART, Bb), 256>>>(x);
    ln_final<<<Bb, 32>>>();
    ln_apply<<<(Mrows*Dd)/4/256, 256>>>(x, h);

    // QKV projections
    gemm_tn<false,false><<<gProj, 256>>>(h, wq, bq, nullptr, q, Dd, Dd);
    gemm_tn<false,false><<<gProj, 256>>>(h, wk, bk, nullptr, k, Dd, Dd);
    gemm_tn<false,false><<<gProj, 256>>>(h, wv, bv, nullptr, v, Dd, Dd);

    // attention
    attn_kernel<<<dim3(Ls/64, Hh, Bb), 256>>>(q, k, v, o);

    // output projection + residual (x)
    gemm_tn<false,true><<<gProj, 256>>>(o, wo, bo, x, r1, Dd, Dd);

    // LN2
    ln_partial<<<dim3(NPART, Bb), 256>>>(r1);
    ln_final<<<Bb, 32>>>();
    ln_apply<<<(Mrows*Dd)/4/256, 256>>>(r1, y);

    // FFN
    gemm_tn<true,false><<<gFF1, 256>>>(y, w1, b1, nullptr, f, FFd, Dd);
    gemm_tn<false,true><<<gProj, 256>>>(f, w2, b2, x, out, Dd, FFd);
}

// round 6
// speedup vs baseline: 1.4488x; 1.4488x over previous
#include <cuda_runtime.h>
#include <cuda_bf16.h>
#include <math.h>
#include <stdint.h>

// Problem constants
#define Bb   2
#define Ls   2048
#define Dd   1024
#define Hh   16
#define DHd  64
#define FFd  4096
#define Mrows (Bb*Ls)      // 4096
#define LD    (Ls*Dd)      // 2097152
#define NPART 64

// ---------------- scratch (static device globals; no allocation) -------------
__device__ float g_q[Mrows*Dd];
__device__ float g_k[Mrows*Dd];
__device__ float g_v[Mrows*Dd];
__device__ float g_o[Mrows*Dd];
__device__ float g_r1[Mrows*Dd];
__device__ float g_part[Bb*NPART*2];
__device__ float g_stats[Bb*2];

// bf16 hi/lo split buffers (16B-aligned for cp.async)
__device__ __align__(256) __nv_bfloat16 g_wqh[Dd*Dd];
__device__ __align__(256) __nv_bfloat16 g_wql[Dd*Dd];
__device__ __align__(256) __nv_bfloat16 g_wkh[Dd*Dd];
__device__ __align__(256) __nv_bfloat16 g_wkl[Dd*Dd];
__device__ __align__(256) __nv_bfloat16 g_wvh[Dd*Dd];
__device__ __align__(256) __nv_bfloat16 g_wvl[Dd*Dd];
__device__ __align__(256) __nv_bfloat16 g_woh[Dd*Dd];
__device__ __align__(256) __nv_bfloat16 g_wol[Dd*Dd];
__device__ __align__(256) __nv_bfloat16 g_w1h[FFd*Dd];
__device__ __align__(256) __nv_bfloat16 g_w1l[FFd*Dd];
__device__ __align__(256) __nv_bfloat16 g_w2h[Dd*FFd];
__device__ __align__(256) __nv_bfloat16 g_w2l[Dd*FFd];
__device__ __align__(256) __nv_bfloat16 g_hh[Mrows*Dd];
__device__ __align__(256) __nv_bfloat16 g_hl[Mrows*Dd];
__device__ __align__(256) __nv_bfloat16 g_yh[Mrows*Dd];
__device__ __align__(256) __nv_bfloat16 g_yl[Mrows*Dd];
__device__ __align__(256) __nv_bfloat16 g_oh[Mrows*Dd];
__device__ __align__(256) __nv_bfloat16 g_ol[Mrows*Dd];
__device__ __align__(256) __nv_bfloat16 g_fh[Mrows*FFd];
__device__ __align__(256) __nv_bfloat16 g_fl[Mrows*FFd];

// ---------------- PTX helpers (all legal on plain sm_103) ---------------------
__device__ __forceinline__ uint32_t smem_u32(const void* p) {
    uint32_t a;
    asm("{ .reg .u64 t; cvta.to.shared.u64 t, %1; cvt.u32.u64 %0, t; }" : "=r"(a) : "l"(p));
    return a;
}
__device__ __forceinline__ void cp16(uint32_t dst, const void* src) {
    asm volatile("cp.async.cg.shared.global [%0], [%1], 16;" :: "r"(dst), "l"(src) : "memory");
}
__device__ __forceinline__ void ldsm4(uint32_t* r, uint32_t addr) {
    asm volatile("ldmatrix.sync.aligned.m8n8.x4.shared.b16 {%0,%1,%2,%3}, [%4];"
                 : "=r"(r[0]), "=r"(r[1]), "=r"(r[2]), "=r"(r[3]) : "r"(addr));
}
__device__ __forceinline__ void mma_bf16(float* c, const uint32_t* a, uint32_t b0, uint32_t b1) {
    asm volatile(
        "mma.sync.aligned.m16n8k16.row.col.f32.bf16.bf16.f32 "
        "{%0,%1,%2,%3}, {%4,%5,%6,%7}, {%8,%9}, {%0,%1,%2,%3};"
        : "+f"(c[0]), "+f"(c[1]), "+f"(c[2]), "+f"(c[3])
        : "r"(a[0]), "r"(a[1]), "r"(a[2]), "r"(a[3]), "r"(b0), "r"(b1));
}

// ---------------- fp32 -> bf16 hi/lo split kernels ----------------------------
__global__ void split_kernel(const float* __restrict__ in,
                             __nv_bfloat16* __restrict__ hi, __nv_bfloat16* __restrict__ lo) {
    const int idx = blockIdx.x * 256 + threadIdx.x;    // float4 index
    float4 v = ((const float4*)in)[idx];
    __nv_bfloat16 h0 = __float2bfloat16(v.x), h1 = __float2bfloat16(v.y);
    __nv_bfloat16 h2 = __float2bfloat16(v.z), h3 = __float2bfloat16(v.w);
    __nv_bfloat16 l0 = __float2bfloat16(v.x - __bfloat162float(h0));
    __nv_bfloat16 l1 = __float2bfloat16(v.y - __bfloat162float(h1));
    __nv_bfloat16 l2 = __float2bfloat16(v.z - __bfloat162float(h2));
    __nv_bfloat16 l3 = __float2bfloat16(v.w - __bfloat162float(h3));
    ((__nv_bfloat162*)hi)[2*idx]   = {h0, h1};
    ((__nv_bfloat162*)hi)[2*idx+1] = {h2, h3};
    ((__nv_bfloat162*)lo)[2*idx]   = {l0, l1};
    ((__nv_bfloat162*)lo)[2*idx+1] = {l2, l3};
}

// ---------------- LayerNorm over (L,D) jointly per batch ---------------------
__global__ void ln_partial(const float* __restrict__ x) {
    const int b = blockIdx.y;
    const int tid = threadIdx.x;
    const int chunk4 = (LD / NPART) / 4;
    const float4* xp = (const float4*)(x + (size_t)b * LD) + (size_t)blockIdx.x * chunk4;
    float s = 0.f, s2 = 0.f;
    for (int i = tid; i < chunk4; i += 256) {
        float4 v = xp[i];
        s  += v.x + v.y + v.z + v.w;
        s2 += v.x*v.x + v.y*v.y + v.z*v.z + v.w*v.w;
    }
    __shared__ float sh[2][256];
    sh[0][tid] = s; sh[1][tid] = s2;
    __syncthreads();
    for (int st = 128; st > 0; st >>= 1) {
        if (tid < st) { sh[0][tid] += sh[0][tid+st]; sh[1][tid] += sh[1][tid+st]; }
        __syncthreads();
    }
    if (tid == 0) {
        g_part[(b*NPART + blockIdx.x)*2 + 0] = sh[0][0];
        g_part[(b*NPART + blockIdx.x)*2 + 1] = sh[1][0];
    }
}

__global__ void ln_final() {
    const int b = blockIdx.x, t = threadIdx.x;   // 32 threads
    float s  = g_part[(b*NPART + t)*2 + 0] + g_part[(b*NPART + t + 32)*2 + 0];
    float s2 = g_part[(b*NPART + t)*2 + 1] + g_part[(b*NPART + t + 32)*2 + 1];
    for (int o = 16; o; o >>= 1) {
        s  += __shfl_xor_sync(0xffffffffu, s,  o);
        s2 += __shfl_xor_sync(0xffffffffu, s2, o);
    }
    if (t == 0) {
        float mu  = s / (float)LD;
        float var = s2 / (float)LD - mu*mu;
        g_stats[b*2 + 0] = mu;
        g_stats[b*2 + 1] = rsqrtf(var + 1e-5f);
    }
}

__global__ void ln_apply_split(const float* __restrict__ in,
                               __nv_bfloat16* __restrict__ hi, __nv_bfloat16* __restrict__ lo) {
    const int idx = blockIdx.x * blockDim.x + threadIdx.x;   // float4 index
    const int b = idx / (LD/4);
    const float mu = g_stats[b*2 + 0], rs = g_stats[b*2 + 1];
    float4 v = ((const float4*)in)[idx];
    v.x = (v.x - mu) * rs; v.y = (v.y - mu) * rs;
    v.z = (v.z - mu) * rs; v.w = (v.w - mu) * rs;
    __nv_bfloat16 h0 = __float2bfloat16(v.x), h1 = __float2bfloat16(v.y);
    __nv_bfloat16 h2 = __float2bfloat16(v.z), h3 = __float2bfloat16(v.w);
    __nv_bfloat16 l0 = __float2bfloat16(v.x - __bfloat162float(h0));
    __nv_bfloat16 l1 = __float2bfloat16(v.y - __bfloat162float(h1));
    __nv_bfloat16 l2 = __float2bfloat16(v.z - __bfloat162float(h2));
    __nv_bfloat16 l3 = __float2bfloat16(v.w - __bfloat162float(h3));
    ((__nv_bfloat162*)hi)[2*idx]   = {h0, h1};
    ((__nv_bfloat162*)hi)[2*idx+1] = {h2, h3};
    ((__nv_bfloat162*)lo)[2*idx]   = {l0, l1};
    ((__nv_bfloat162*)lo)[2*idx+1] = {l2, l3};
}

// ---------------- mma.sync split-bf16 GEMM ------------------------------------
// C[M,N] = A[M,K] @ W[N,K]^T via AhBh + AlBh + AhBl, fp32 accum.
// 128x128 CTA tile, BK=32, double-buffered cp.async.
// SMEM: per stage 4 tiles (Ah, Al, Bh, Bl), each 128 rows x 32 bf16,
// row stride 80B (64B data + 16B pad -> conflict-free ldmatrix).
#define TILE_B   10240              // 128 * 80
#define STAGE_B  (4*TILE_B)         // 40960
#define GEMM_SMEM (2*STAGE_B)       // 81920

template<bool RELU, bool RESID, bool SPLIT>
__global__ __launch_bounds__(256)
void gemm_mma(const __nv_bfloat16* __restrict__ Ah, const __nv_bfloat16* __restrict__ Al,
              const __nv_bfloat16* __restrict__ Bh, const __nv_bfloat16* __restrict__ Bl,
              const float* __restrict__ bias, const float* __restrict__ R,
              float* __restrict__ C,
              __nv_bfloat16* __restrict__ Ch, __nv_bfloat16* __restrict__ Cl,
              int Ndim, int Kdim)
{
    extern __shared__ char smem[];
    const uint32_t sb = smem_u32(smem);
    const int tid  = threadIdx.x;
    const int wid  = tid >> 5, lane = tid & 31;
    const int wm   = wid & 3;          // warp row group (32 rows)
    const int wn   = wid >> 2;         // warp col group (64 cols)
    const int bm   = blockIdx.y * 128, bn = blockIdx.x * 128;

    float acc[2][8][4];
    #pragma unroll
    for (int i = 0; i < 2; i++)
        #pragma unroll
        for (int j = 0; j < 8; j++)
            #pragma unroll
            for (int t = 0; t < 4; t++) acc[i][j][t] = 0.f;

    // per-thread load mapping: 2 chunks of 16B per tile per stage
    const int r0c = tid >> 2, c0c = tid & 3;            // chunk 0: id = tid
    const int r1c = (tid + 256) >> 2, c1c = tid & 3;    // chunk 1: id = tid+256

    auto load_stage = [&](int s, int k0) {
        const uint32_t st = sb + s * STAGE_B;
        cp16(st + 0*TILE_B + r0c*80 + c0c*16, Ah + (size_t)(bm + r0c)*Kdim + k0 + c0c*8);
        cp16(st + 0*TILE_B + r1c*80 + c1c*16, Ah + (size_t)(bm + r1c)*Kdim + k0 + c1c*8);
        cp16(st + 1*TILE_B + r0c*80 + c0c*16, Al + (size_t)(bm + r0c)*Kdim + k0 + c0c*8);
        cp16(st + 1*TILE_B + r1c*80 + c1c*16, Al + (size_t)(bm + r1c)*Kdim + k0 + c1c*8);
        cp16(st + 2*TILE_B + r0c*80 + c0c*16, Bh + (size_t)(bn + r0c)*Kdim + k0 + c0c*8);
        cp16(st + 2*TILE_B + r1c*80 + c1c*16, Bh + (size_t)(bn + r1c)*Kdim + k0 + c1c*8);
        cp16(st + 3*TILE_B + r0c*80 + c0c*16, Bl + (size_t)(bn + r0c)*Kdim + k0 + c0c*8);
        cp16(st + 3*TILE_B + r1c*80 + c1c*16, Bl + (size_t)(bn + r1c)*Kdim + k0 + c1c*8);
        asm volatile("cp.async.commit_group;" ::: "memory");
    };

    const int nk = Kdim >> 5;
    load_stage(0, 0);

    for (int kt = 0; kt < nk; kt++) {
        if (kt + 1 < nk) {
            load_stage((kt + 1) & 1, (kt + 1) << 5);
            asm volatile("cp.async.wait_group 1;" ::: "memory");
        } else {
            asm volatile("cp.async.wait_group 0;" ::: "memory");
        }
        __syncthreads();

        const uint32_t st = sb + (kt & 1) * STAGE_B;
        #pragma unroll
        for (int ks = 0; ks < 2; ks++) {
            const uint32_t koff = ks*32 + ((lane >> 4) & 1)*16;
            uint32_t ah[2][4], al[2][4];
            #pragma unroll
            for (int mt = 0; mt < 2; mt++) {
                const uint32_t ra = st + (wm*32 + mt*16 + (lane & 15))*80 + koff;
                ldsm4(ah[mt], ra);
                ldsm4(al[mt], ra + TILE_B);
            }
            #pragma unroll
            for (int g = 0; g < 4; g++) {
                const uint32_t rb = st + 2*TILE_B + (wn*64 + g*16 + (lane & 15))*80 + koff;
                uint32_t bh[4], bl[4];
                ldsm4(bh, rb);
                ldsm4(bl, rb + TILE_B);
                #pragma unroll
                for (int mt = 0; mt < 2; mt++) {
                    float* cA = acc[mt][2*g];
                    float* cB = acc[mt][2*g+1];
                    mma_bf16(cA, ah[mt], bh[0], bh[2]);
                    mma_bf16(cB, ah[mt], bh[1], bh[3]);
                    mma_bf16(cA, al[mt], bh[0], bh[2]);
                    mma_bf16(cB, al[mt], bh[1], bh[3]);
                    mma_bf16(cA, ah[mt], bl[0], bl[2]);
                    mma_bf16(cB, ah[mt], bl[1], bl[3]);
                }
            }
        }
        __syncthreads();
    }

    // ---- epilogue ----
    #pragma unroll
    for (int mt = 0; mt < 2; mt++) {
        const int row0 = bm + wm*32 + mt*16 + (lane >> 2);
        #pragma unroll
        for (int nt = 0; nt < 8; nt++) {
            const int cc = bn + wn*64 + nt*8 + (lane & 3)*2;
            const float b0 = bias[cc], b1 = bias[cc+1];
            float v00 = acc[mt][nt][0] + b0, v01 = acc[mt][nt][1] + b1;
            float v10 = acc[mt][nt][2] + b0, v11 = acc[mt][nt][3] + b1;
            if (RESID) {
                v00 += R[(size_t)row0*Ndim + cc];     v01 += R[(size_t)row0*Ndim + cc + 1];
                v10 += R[(size_t)(row0+8)*Ndim + cc]; v11 += R[(size_t)(row0+8)*Ndim + cc + 1];
            }
            if (RELU) {
                v00 = fmaxf(v00, 0.f); v01 = fmaxf(v01, 0.f);
                v10 = fmaxf(v10, 0.f); v11 = fmaxf(v11, 0.f);
            }
            if (SPLIT) {
                __nv_bfloat16 h00 = __float2bfloat16(v00), h01 = __float2bfloat16(v01);
                __nv_bfloat16 h10 = __float2bfloat16(v10), h11 = __float2bfloat16(v11);
                __nv_bfloat16 l00 = __float2bfloat16(v00 - __bfloat162float(h00));
                __nv_bfloat16 l01 = __float2bfloat16(v01 - __bfloat162float(h01));
                __nv_bfloat16 l10 = __float2bfloat16(v10 - __bfloat162float(h10));
                __nv_bfloat16 l11 = __float2bfloat16(v11 - __bfloat162float(h11));
                *(__nv_bfloat162*)(Ch + (size_t)row0*Ndim + cc)     = {h00, h01};
                *(__nv_bfloat162*)(Ch + (size_t)(row0+8)*Ndim + cc) = {h10, h11};
                *(__nv_bfloat162*)(Cl + (size_t)row0*Ndim + cc)     = {l00, l01};
                *(__nv_bfloat162*)(Cl + (size_t)(row0+8)*Ndim + cc) = {l10, l11};
            } else {
                *(float2*)(C + (size_t)row0*Ndim + cc)     = {v00, v01};
                *(float2*)(C + (size_t)(row0+8)*Ndim + cc) = {v10, v11};
            }
        }
    }
}

// ---------------- Flash attention (SIMT, validated in R4) ---------------------
__global__ __launch_bounds__(256)
void attn_kernel(const float* __restrict__ q, const float* __restrict__ k,
                 const float* __restrict__ v, float* __restrict__ o)
{
    __shared__ float Qs[64][68];
    __shared__ float Ks[32][68];
    __shared__ float Vs[32][68];
    __shared__ float Ss[64][33];

    const int b = blockIdx.z, hh = blockIdx.y, q0 = blockIdx.x * 64;
    const int tid = threadIdx.x;

    {
        const int r = tid >> 2, cb = (tid & 3) * 16;
        const float* src = q + ((size_t)(b*Ls + q0 + r) * Dd) + hh*DHd + cb;
        #pragma unroll
        for (int i = 0; i < 16; i += 4) {
            float4 t = *(const float4*)(src + i);
            Qs[r][cb+i] = t.x; Qs[r][cb+i+1] = t.y; Qs[r][cb+i+2] = t.z; Qs[r][cb+i+3] = t.w;
        }
    }

    const int row = tid >> 2;
    const int cg  = tid & 3;
    float m = -1e30f, l = 0.f;
    float4 a0 = {0,0,0,0}, a1 = {0,0,0,0}, a2 = {0,0,0,0}, a3 = {0,0,0,0};

    __syncthreads();

    for (int t0 = 0; t0 < Ls; t0 += 32) {
        {
            const int r = tid >> 3, cb = (tid & 7) * 8;
            const float* ks = k + ((size_t)(b*Ls + t0 + r) * Dd) + hh*DHd + cb;
            const float* vs = v + ((size_t)(b*Ls + t0 + r) * Dd) + hh*DHd + cb;
            float4 t1 = *(const float4*)ks, t2 = *(const float4*)(ks + 4);
            Ks[r][cb+0]=t1.x; Ks[r][cb+1]=t1.y; Ks[r][cb+2]=t1.z; Ks[r][cb+3]=t1.w;
            Ks[r][cb+4]=t2.x; Ks[r][cb+5]=t2.y; Ks[r][cb+6]=t2.z; Ks[r][cb+7]=t2.w;
            float4 t3 = *(const float4*)vs, t4 = *(const float4*)(vs + 4);
            Vs[r][cb+0]=t3.x; Vs[r][cb+1]=t3.y; Vs[r][cb+2]=t3.z; Vs[r][cb+3]=t3.w;
            Vs[r][cb+4]=t4.x; Vs[r][cb+5]=t4.y; Vs[r][cb+6]=t4.z; Vs[r][cb+7]=t4.w;
        }
        __syncthreads();

        {
            const int sr = (tid >> 3) * 2;
            const int sc = tid & 7;
            float s0[4] = {0,0,0,0}, s1[4] = {0,0,0,0};
            #pragma unroll
            for (int d = 0; d < 64; d += 4) {
                float4 qa = *(const float4*)&Qs[sr][d];
                float4 qb = *(const float4*)&Qs[sr+1][d];
                #pragma unroll
                for (int j = 0; j < 4; j++) {
                    float4 kv = *(const float4*)&Ks[sc + 8*j][d];
                    s0[j] += qa.x*kv.x + qa.y*kv.y + qa.z*kv.z + qa.w*kv.w;
                    s1[j] += qb.x*kv.x + qb.y*kv.y + qb.z*kv.z + qb.w*kv.w;
                }
            }
            #pragma unroll
            for (int j = 0; j < 4; j++) {
                Ss[sr  ][sc + 8*j] = s0[j] * 0.25f;
                Ss[sr+1][sc + 8*j] = s1[j] * 0.25f;
            }
        }
        __syncthreads();

        float pv[8], pm = -1e30f;
        #pragma unroll
        for (int j = 0; j < 8; j++) { pv[j] = Ss[row][cg*8 + j]; pm = fmaxf(pm, pv[j]); }
        pm = fmaxf(pm, __shfl_xor_sync(0xffffffffu, pm, 1));
        pm = fmaxf(pm, __shfl_xor_sync(0xffffffffu, pm, 2));
        const float nm = fmaxf(m, pm);
        const float corr = __expf(m - nm);
        float ps = 0.f;
        #pragma unroll
        for (int j = 0; j < 8; j++) {
            pv[j] = __expf(pv[j] - nm);
            ps += pv[j];
            Ss[row][cg*8 + j] = pv[j];
        }
        ps += __shfl_xor_sync(0xffffffffu, ps, 1);
        ps += __shfl_xor_sync(0xffffffffu, ps, 2);
        l = l * corr + ps;
        m = nm;
        a0.x*=corr; a0.y*=corr; a0.z*=corr; a0.w*=corr;
        a1.x*=corr; a1.y*=corr; a1.z*=corr; a1.w*=corr;
        a2.x*=corr; a2.y*=corr; a2.z*=corr; a2.w*=corr;
        a3.x*=corr; a3.y*=corr; a3.z*=corr; a3.w*=corr;
        __syncwarp();

        #pragma unroll
        for (int kk = 0; kk < 32; kk++) {
            const float p = Ss[row][kk];
            const float4* vr = (const float4*)&Vs[kk][cg*16];
            float4 v0 = vr[0], v1 = vr[1], v2 = vr[2], v3 = vr[3];
            a0.x += p*v0.x; a0.y += p*v0.y; a0.z += p*v0.z; a0.w += p*v0.w;
            a1.x += p*v1.x; a1.y += p*v1.y; a1.z += p*v1.z; a1.w += p*v1.w;
            a2.x += p*v2.x; a2.y += p*v2.y; a2.z += p*v2.z; a2.w += p*v2.w;
            a3.x += p*v3.x; a3.y += p*v3.y; a3.z += p*v3.z; a3.w += p*v3.w;
        }
        __syncthreads();
    }

    const float inv = 1.f / l;
    float* dst = o + ((size_t)(b*Ls + q0 + row) * Dd) + hh*DHd + cg*16;
    float4 w0 = {a0.x*inv, a0.y*inv, a0.z*inv, a0.w*inv};
    float4 w1 = {a1.x*inv, a1.y*inv, a1.z*inv, a1.w*inv};
    float4 w2 = {a2.x*inv, a2.y*inv, a2.z*inv, a2.w*inv};
    float4 w3 = {a3.x*inv, a3.y*inv, a3.z*inv, a3.w*inv};
    ((float4*)dst)[0] = w0; ((float4*)dst)[1] = w1;
    ((float4*)dst)[2] = w2; ((float4*)dst)[3] = w3;
}

// ---------------- host orchestration ----------------------------------------
extern "C" void kernel_launch(void* const* d_in, const int* in_sizes, int n_in,
                              void* d_out, int out_size)
{
    (void)in_sizes; (void)n_in; (void)out_size;
    const float* x  = (const float*)d_in[0];
    const float* wq = (const float*)d_in[1];
    const float* bq = (const float*)d_in[2];
    const float* wk = (const float*)d_in[3];
    const float* bk = (const float*)d_in[4];
    const float* wv = (const float*)d_in[5];
    const float* bv = (const float*)d_in[6];
    const float* wo = (const float*)d_in[7];
    const float* bo = (const float*)d_in[8];
    const float* w1 = (const float*)d_in[9];
    const float* b1 = (const float*)d_in[10];
    const float* w2 = (const float*)d_in[11];
    const float* b2 = (const float*)d_in[12];
    float* out = (float*)d_out;

    float *q, *k, *v, *o, *r1;
    cudaGetSymbolAddress((void**)&q,  g_q);
    cudaGetSymbolAddress((void**)&k,  g_k);
    cudaGetSymbolAddress((void**)&v,  g_v);
    cudaGetSymbolAddress((void**)&o,  g_o);
    cudaGetSymbolAddress((void**)&r1, g_r1);

    __nv_bfloat16 *wqh,*wql,*wkh,*wkl,*wvh,*wvl,*woh,*wol,*w1h,*w1l,*w2h,*w2l;
    __nv_bfloat16 *hh,*hl,*yh,*yl,*oh,*ol,*fh,*fl;
    cudaGetSymbolAddress((void**)&wqh, g_wqh); cudaGetSymbolAddress((void**)&wql, g_wql);
    cudaGetSymbolAddress((void**)&wkh, g_wkh); cudaGetSymbolAddress((void**)&wkl, g_wkl);
    cudaGetSymbolAddress((void**)&wvh, g_wvh); cudaGetSymbolAddress((void**)&wvl, g_wvl);
    cudaGetSymbolAddress((void**)&woh, g_woh); cudaGetSymbolAddress((void**)&wol, g_wol);
    cudaGetSymbolAddress((void**)&w1h, g_w1h); cudaGetSymbolAddress((void**)&w1l, g_w1l);
    cudaGetSymbolAddress((void**)&w2h, g_w2h); cudaGetSymbolAddress((void**)&w2l, g_w2l);
    cudaGetSymbolAddress((void**)&hh,  g_hh);  cudaGetSymbolAddress((void**)&hl,  g_hl);
    cudaGetSymbolAddress((void**)&yh,  g_yh);  cudaGetSymbolAddress((void**)&yl,  g_yl);
    cudaGetSymbolAddress((void**)&oh,  g_oh);  cudaGetSymbolAddress((void**)&ol,  g_ol);
    cudaGetSymbolAddress((void**)&fh,  g_fh);  cudaGetSymbolAddress((void**)&fl,  g_fl);

    cudaFuncSetAttribute(gemm_mma<false,false,false>, cudaFuncAttributeMaxDynamicSharedMemorySize, GEMM_SMEM);
    cudaFuncSetAttribute(gemm_mma<false,true, false>, cudaFuncAttributeMaxDynamicSharedMemorySize, GEMM_SMEM);
    cudaFuncSetAttribute(gemm_mma<true, false,true >, cudaFuncAttributeMaxDynamicSharedMemorySize, GEMM_SMEM);

    const dim3 gProj(Dd/128, Mrows/128);     // (8, 32)
    const dim3 gFF1(FFd/128, Mrows/128);     // (32, 32)

    // weight splits
    split_kernel<<<(Dd*Dd)/1024, 256>>>(wq, wqh, wql);
    split_kernel<<<(Dd*Dd)/1024, 256>>>(wk, wkh, wkl);
    split_kernel<<<(Dd*Dd)/1024, 256>>>(wv, wvh, wvl);
    split_kernel<<<(Dd*Dd)/1024, 256>>>(wo, woh, wol);
    split_kernel<<<(FFd*Dd)/1024, 256>>>(w1, w1h, w1l);
    split_kernel<<<(Dd*FFd)/1024, 256>>>(w2, w2h, w2l);

    // LN1 -> h (hi/lo)
    ln_partial<<<dim3(NPART, Bb), 256>>>(x);
    ln_final<<<Bb, 32>>>();
    ln_apply_split<<<(Mrows*Dd)/4/256, 256>>>(x, hh, hl);

    // QKV projections (fp32 out for attention)
    gemm_mma<false,false,false><<<gProj, 256, GEMM_SMEM>>>(hh, hl, wqh, wql, bq, nullptr, q, nullptr, nullptr, Dd, Dd);
    gemm_mma<false,false,false><<<gProj, 256, GEMM_SMEM>>>(hh, hl, wkh, wkl, bk, nullptr, k, nullptr, nullptr, Dd, Dd);
    gemm_mma<false,false,false><<<gProj, 256, GEMM_SMEM>>>(hh, hl, wvh, wvl, bv, nullptr, v, nullptr, nullptr, Dd, Dd);

    // attention
    attn_kernel<<<dim3(Ls/64, Hh, Bb), 256>>>(q, k, v, o);

    // split attention output, then out-proj + residual(x)
    split_kernel<<<(Mrows*Dd)/1024, 256>>>(o, oh, ol);
    gemm_mma<false,true,false><<<gProj, 256, GEMM_SMEM>>>(oh, ol, woh, wol, bo, x, r1, nullptr, nullptr, Dd, Dd);

    // LN2 -> y (hi/lo)
    ln_partial<<<dim3(NPART, Bb), 256>>>(r1);
    ln_final<<<Bb, 32>>>();
    ln_apply_split<<<(Mrows*Dd)/4/256, 256>>>(r1, yh, yl);

    // FFN1: relu, emit bf16 hi/lo directly
    gemm_mma<true,false,true><<<gFF1, 256, GEMM_SMEM>>>(yh, yl, w1h, w1l, b1, nullptr, nullptr, fh, fl, FFd, Dd);
    // FFN2: + residual(x), fp32 out
    gemm_mma<false,true,false><<<gProj, 256, GEMM_SMEM>>>(fh, fl, w2h, w2l, b2, x, out, nullptr, nullptr, Dd, FFd);
}

// round 8
// speedup vs baseline: 3.7537x; 2.5910x over previous
#include <cuda_runtime.h>
#include <cuda_bf16.h>
#include <math.h>
#include <stdint.h>

// Problem constants
#define Bb   2
#define Ls   2048
#define Dd   1024
#define Hh   16
#define DHd  64
#define FFd  4096
#define Mrows (Bb*Ls)      // 4096
#define LD    (Ls*Dd)      // 2097152
#define NPART 64

// ---------------- scratch (static device globals; no allocation) -------------
__device__ float g_r1[Mrows*Dd];
__device__ float g_part[Bb*NPART*2];
__device__ float g_stats[Bb*2];

// bf16 hi/lo split buffers (aligned for cp.async)
__device__ __align__(256) __nv_bfloat16 g_wqh[Dd*Dd];
__device__ __align__(256) __nv_bfloat16 g_wql[Dd*Dd];
__device__ __align__(256) __nv_bfloat16 g_wkh[Dd*Dd];
__device__ __align__(256) __nv_bfloat16 g_wkl[Dd*Dd];
__device__ __align__(256) __nv_bfloat16 g_wvh[Dd*Dd];
__device__ __align__(256) __nv_bfloat16 g_wvl[Dd*Dd];
__device__ __align__(256) __nv_bfloat16 g_woh[Dd*Dd];
__device__ __align__(256) __nv_bfloat16 g_wol[Dd*Dd];
__device__ __align__(256) __nv_bfloat16 g_w1h[FFd*Dd];
__device__ __align__(256) __nv_bfloat16 g_w1l[FFd*Dd];
__device__ __align__(256) __nv_bfloat16 g_w2h[Dd*FFd];
__device__ __align__(256) __nv_bfloat16 g_w2l[Dd*FFd];
__device__ __align__(256) __nv_bfloat16 g_hh[Mrows*Dd];
__device__ __align__(256) __nv_bfloat16 g_hl[Mrows*Dd];
__device__ __align__(256) __nv_bfloat16 g_yh[Mrows*Dd];
__device__ __align__(256) __nv_bfloat16 g_yl[Mrows*Dd];
__device__ __align__(256) __nv_bfloat16 g_oh[Mrows*Dd];
__device__ __align__(256) __nv_bfloat16 g_ol[Mrows*Dd];
__device__ __align__(256) __nv_bfloat16 g_fh[Mrows*FFd];
__device__ __align__(256) __nv_bfloat16 g_fl[Mrows*FFd];
__device__ __align__(256) __nv_bfloat16 g_qh[Mrows*Dd];
__device__ __align__(256) __nv_bfloat16 g_ql[Mrows*Dd];
__device__ __align__(256) __nv_bfloat16 g_kh[Mrows*Dd];
__device__ __align__(256) __nv_bfloat16 g_kl[Mrows*Dd];
__device__ __align__(256) __nv_bfloat16 g_vh[Mrows*Dd];
__device__ __align__(256) __nv_bfloat16 g_vl[Mrows*Dd];

// ---------------- PTX helpers (all legal on plain sm_103) ---------------------
__device__ __forceinline__ uint32_t smem_u32(const void* p) {
    uint32_t a;
    asm("{ .reg .u64 t; cvta.to.shared.u64 t, %1; cvt.u32.u64 %0, t; }" : "=r"(a) : "l"(p));
    return a;
}
__device__ __forceinline__ void cp16(uint32_t dst, const void* src) {
    asm volatile("cp.async.cg.shared.global [%0], [%1], 16;" :: "r"(dst), "l"(src) : "memory");
}
__device__ __forceinline__ void ldsm4(uint32_t* r, uint32_t addr) {
    asm volatile("ldmatrix.sync.aligned.m8n8.x4.shared.b16 {%0,%1,%2,%3}, [%4];"
                 : "=r"(r[0]), "=r"(r[1]), "=r"(r[2]), "=r"(r[3]) : "r"(addr));
}
__device__ __forceinline__ void ldsm4t(uint32_t* r, uint32_t addr) {
    asm volatile("ldmatrix.sync.aligned.m8n8.x4.trans.shared.b16 {%0,%1,%2,%3}, [%4];"
                 : "=r"(r[0]), "=r"(r[1]), "=r"(r[2]), "=r"(r[3]) : "r"(addr));
}
__device__ __forceinline__ void mma_bf16(float* c, const uint32_t* a, uint32_t b0, uint32_t b1) {
    asm volatile(
        "mma.sync.aligned.m16n8k16.row.col.f32.bf16.bf16.f32 "
        "{%0,%1,%2,%3}, {%4,%5,%6,%7}, {%8,%9}, {%0,%1,%2,%3};"
        : "+f"(c[0]), "+f"(c[1]), "+f"(c[2]), "+f"(c[3])
        : "r"(a[0]), "r"(a[1]), "r"(a[2]), "r"(a[3]), "r"(b0), "r"(b1));
}
__device__ __forceinline__ uint32_t f2bf2(float lo, float hi) {
    __nv_bfloat162 t = __floats2bfloat162_rn(lo, hi);
    return *reinterpret_cast<uint32_t*>(&t);
}

// ---------------- fp32 -> bf16 hi/lo split kernels ----------------------------
__global__ void split_kernel(const float* __restrict__ in,
                             __nv_bfloat16* __restrict__ hi, __nv_bfloat16* __restrict__ lo) {
    const int idx = blockIdx.x * 256 + threadIdx.x;    // float4 index
    float4 v = ((const float4*)in)[idx];
    __nv_bfloat16 h0 = __float2bfloat16(v.x), h1 = __float2bfloat16(v.y);
    __nv_bfloat16 h2 = __float2bfloat16(v.z), h3 = __float2bfloat16(v.w);
    __nv_bfloat16 l0 = __float2bfloat16(v.x - __bfloat162float(h0));
    __nv_bfloat16 l1 = __float2bfloat16(v.y - __bfloat162float(h1));
    __nv_bfloat16 l2 = __float2bfloat16(v.z - __bfloat162float(h2));
    __nv_bfloat16 l3 = __float2bfloat16(v.w - __bfloat162float(h3));
    ((__nv_bfloat162*)hi)[2*idx]   = {h0, h1};
    ((__nv_bfloat162*)hi)[2*idx+1] = {h2, h3};
    ((__nv_bfloat162*)lo)[2*idx]   = {l0, l1};
    ((__nv_bfloat162*)lo)[2*idx+1] = {l2, l3};
}

// ---------------- LayerNorm over (L,D) jointly per batch ---------------------
__global__ void ln_partial(const float* __restrict__ x) {
    const int b = blockIdx.y;
    const int tid = threadIdx.x;
    const int chunk4 = (LD / NPART) / 4;
    const float4* xp = (const float4*)(x + (size_t)b * LD) + (size_t)blockIdx.x * chunk4;
    float s = 0.f, s2 = 0.f;
    for (int i = tid; i < chunk4; i += 256) {
        float4 v = xp[i];
        s  += v.x + v.y + v.z + v.w;
        s2 += v.x*v.x + v.y*v.y + v.z*v.z + v.w*v.w;
    }
    __shared__ float sh[2][256];
    sh[0][tid] = s; sh[1][tid] = s2;
    __syncthreads();
    for (int st = 128; st > 0; st >>= 1) {
        if (tid < st) { sh[0][tid] += sh[0][tid+st]; sh[1][tid] += sh[1][tid+st]; }
        __syncthreads();
    }
    if (tid == 0) {
        g_part[(b*NPART + blockIdx.x)*2 + 0] = sh[0][0];
        g_part[(b*NPART + blockIdx.x)*2 + 1] = sh[1][0];
    }
}

__global__ void ln_final() {
    const int b = blockIdx.x, t = threadIdx.x;   // 32 threads
    float s  = g_part[(b*NPART + t)*2 + 0] + g_part[(b*NPART + t + 32)*2 + 0];
    float s2 = g_part[(b*NPART + t)*2 + 1] + g_part[(b*NPART + t + 32)*2 + 1];
    for (int o = 16; o; o >>= 1) {
        s  += __shfl_xor_sync(0xffffffffu, s,  o);
        s2 += __shfl_xor_sync(0xffffffffu, s2, o);
    }
    if (t == 0) {
        float mu  = s / (float)LD;
        float var = s2 / (float)LD - mu*mu;
        g_stats[b*2 + 0] = mu;
        g_stats[b*2 + 1] = rsqrtf(var + 1e-5f);
    }
}

__global__ void ln_apply_split(const float* __restrict__ in,
                               __nv_bfloat16* __restrict__ hi, __nv_bfloat16* __restrict__ lo) {
    const int idx = blockIdx.x * blockDim.x + threadIdx.x;   // float4 index
    const int b = idx / (LD/4);
    const float mu = g_stats[b*2 + 0], rs = g_stats[b*2 + 1];
    float4 v = ((const float4*)in)[idx];
    v.x = (v.x - mu) * rs; v.y = (v.y - mu) * rs;
    v.z = (v.z - mu) * rs; v.w = (v.w - mu) * rs;
    __nv_bfloat16 h0 = __float2bfloat16(v.x), h1 = __float2bfloat16(v.y);
    __nv_bfloat16 h2 = __float2bfloat16(v.z), h3 = __float2bfloat16(v.w);
    __nv_bfloat16 l0 = __float2bfloat16(v.x - __bfloat162float(h0));
    __nv_bfloat16 l1 = __float2bfloat16(v.y - __bfloat162float(h1));
    __nv_bfloat16 l2 = __float2bfloat16(v.z - __bfloat162float(h2));
    __nv_bfloat16 l3 = __float2bfloat16(v.w - __bfloat162float(h3));
    ((__nv_bfloat162*)hi)[2*idx]   = {h0, h1};
    ((__nv_bfloat162*)hi)[2*idx+1] = {h2, h3};
    ((__nv_bfloat162*)lo)[2*idx]   = {l0, l1};
    ((__nv_bfloat162*)lo)[2*idx+1] = {l2, l3};
}

// ---------------- mma.sync split-bf16 GEMM ------------------------------------
#define TILE_B   10240              // 128 * 80
#define STAGE_B  (4*TILE_B)         // 40960
#define GEMM_SMEM (2*STAGE_B)       // 81920

template<bool RELU, bool RESID, bool SPLIT>
__global__ __launch_bounds__(256)
void gemm_mma(const __nv_bfloat16* __restrict__ Ah, const __nv_bfloat16* __restrict__ Al,
              const __nv_bfloat16* __restrict__ Bh, const __nv_bfloat16* __restrict__ Bl,
              const float* __restrict__ bias, const float* __restrict__ R,
              float* __restrict__ C,
              __nv_bfloat16* __restrict__ Ch, __nv_bfloat16* __restrict__ Cl,
              int Ndim, int Kdim)
{
    extern __shared__ char smem[];
    const uint32_t sb = smem_u32(smem);
    const int tid  = threadIdx.x;
    const int wid  = tid >> 5, lane = tid & 31;
    const int wm   = wid & 3;
    const int wn   = wid >> 2;
    const int bm   = blockIdx.y * 128, bn = blockIdx.x * 128;

    float acc[2][8][4];
    #pragma unroll
    for (int i = 0; i < 2; i++)
        #pragma unroll
        for (int j = 0; j < 8; j++)
            #pragma unroll
            for (int t = 0; t < 4; t++) acc[i][j][t] = 0.f;

    const int r0c = tid >> 2, c0c = tid & 3;
    const int r1c = (tid + 256) >> 2, c1c = tid & 3;

    auto load_stage = [&](int s, int k0) {
        const uint32_t st = sb + s * STAGE_B;
        cp16(st + 0*TILE_B + r0c*80 + c0c*16, Ah + (size_t)(bm + r0c)*Kdim + k0 + c0c*8);
        cp16(st + 0*TILE_B + r1c*80 + c1c*16, Ah + (size_t)(bm + r1c)*Kdim + k0 + c1c*8);
        cp16(st + 1*TILE_B + r0c*80 + c0c*16, Al + (size_t)(bm + r0c)*Kdim + k0 + c0c*8);
        cp16(st + 1*TILE_B + r1c*80 + c1c*16, Al + (size_t)(bm + r1c)*Kdim + k0 + c1c*8);
        cp16(st + 2*TILE_B + r0c*80 + c0c*16, Bh + (size_t)(bn + r0c)*Kdim + k0 + c0c*8);
        cp16(st + 2*TILE_B + r1c*80 + c1c*16, Bh + (size_t)(bn + r1c)*Kdim + k0 + c1c*8);
        cp16(st + 3*TILE_B + r0c*80 + c0c*16, Bl + (size_t)(bn + r0c)*Kdim + k0 + c0c*8);
        cp16(st + 3*TILE_B + r1c*80 + c1c*16, Bl + (size_t)(bn + r1c)*Kdim + k0 + c1c*8);
        asm volatile("cp.async.commit_group;" ::: "memory");
    };

    const int nk = Kdim >> 5;
    load_stage(0, 0);

    for (int kt = 0; kt < nk; kt++) {
        if (kt + 1 < nk) {
            load_stage((kt + 1) & 1, (kt + 1) << 5);
            asm volatile("cp.async.wait_group 1;" ::: "memory");
        } else {
            asm volatile("cp.async.wait_group 0;" ::: "memory");
        }
        __syncthreads();

        const uint32_t st = sb + (kt & 1) * STAGE_B;
        #pragma unroll
        for (int ks = 0; ks < 2; ks++) {
            const uint32_t koff = ks*32 + ((lane >> 4) & 1)*16;
            uint32_t ah[2][4], al[2][4];
            #pragma unroll
            for (int mt = 0; mt < 2; mt++) {
                const uint32_t ra = st + (wm*32 + mt*16 + (lane & 15))*80 + koff;
                ldsm4(ah[mt], ra);
                ldsm4(al[mt], ra + TILE_B);
            }
            #pragma unroll
            for (int g = 0; g < 4; g++) {
                const uint32_t rb = st + 2*TILE_B + (wn*64 + g*16 + (lane & 15))*80 + koff;
                uint32_t bh[4], bl[4];
                ldsm4(bh, rb);
                ldsm4(bl, rb + TILE_B);
                #pragma unroll
                for (int mt = 0; mt < 2; mt++) {
                    float* cA = acc[mt][2*g];
                    float* cB = acc[mt][2*g+1];
                    mma_bf16(cA, ah[mt], bh[0], bh[2]);
                    mma_bf16(cB, ah[mt], bh[1], bh[3]);
                    mma_bf16(cA, al[mt], bh[0], bh[2]);
                    mma_bf16(cB, al[mt], bh[1], bh[3]);
                    mma_bf16(cA, ah[mt], bl[0], bl[2]);
                    mma_bf16(cB, ah[mt], bl[1], bl[3]);
                }
            }
        }
        __syncthreads();
    }

    // ---- epilogue ----
    #pragma unroll
    for (int mt = 0; mt < 2; mt++) {
        const int row0 = bm + wm*32 + mt*16 + (lane >> 2);
        #pragma unroll
        for (int nt = 0; nt < 8; nt++) {
            const int cc = bn + wn*64 + nt*8 + (lane & 3)*2;
            const float b0 = bias[cc], b1 = bias[cc+1];
            float v00 = acc[mt][nt][0] + b0, v01 = acc[mt][nt][1] + b1;
            float v10 = acc[mt][nt][2] + b0, v11 = acc[mt][nt][3] + b1;
            if (RESID) {
                v00 += R[(size_t)row0*Ndim + cc];     v01 += R[(size_t)row0*Ndim + cc + 1];
                v10 += R[(size_t)(row0+8)*Ndim + cc]; v11 += R[(size_t)(row0+8)*Ndim + cc + 1];
            }
            if (RELU) {
                v00 = fmaxf(v00, 0.f); v01 = fmaxf(v01, 0.f);
                v10 = fmaxf(v10, 0.f); v11 = fmaxf(v11, 0.f);
            }
            if (SPLIT) {
                __nv_bfloat16 h00 = __float2bfloat16(v00), h01 = __float2bfloat16(v01);
                __nv_bfloat16 h10 = __float2bfloat16(v10), h11 = __float2bfloat16(v11);
                __nv_bfloat16 l00 = __float2bfloat16(v00 - __bfloat162float(h00));
                __nv_bfloat16 l01 = __float2bfloat16(v01 - __bfloat162float(h01));
                __nv_bfloat16 l10 = __float2bfloat16(v10 - __bfloat162float(h10));
                __nv_bfloat16 l11 = __float2bfloat16(v11 - __bfloat162float(h11));
                *(__nv_bfloat162*)(Ch + (size_t)row0*Ndim + cc)     = {h00, h01};
                *(__nv_bfloat162*)(Ch + (size_t)(row0+8)*Ndim + cc) = {h10, h11};
                *(__nv_bfloat162*)(Cl + (size_t)row0*Ndim + cc)     = {l00, l01};
                *(__nv_bfloat162*)(Cl + (size_t)(row0+8)*Ndim + cc) = {l10, l11};
            } else {
                *(float2*)(C + (size_t)row0*Ndim + cc)     = {v00, v01};
                *(float2*)(C + (size_t)(row0+8)*Ndim + cc) = {v10, v11};
            }
        }
    }
}

// ---------------- MMA flash attention -----------------------------------------
// Per CTA: one (b, h), 128 q rows. 8 warps, each owns 16 q rows.
// KV streamed in 64-key chunks, double-buffered cp.async.
// S = Qh*Kh + Ql*Kh + Qh*Kl ; O += Ph*Vh + Pl*Vh + Ph*Vl ; fp32 softmax.
#define AST 144                      // smem row stride bytes (64 bf16 + 16B pad)
#define ATT_QH 0
#define ATT_QL (128*AST)             // 18432
#define ATT_S0 (2*128*AST)           // 36864
#define ATT_STAGE (4*64*AST)         // 36864
#define ATT_KHo 0
#define ATT_KLo (64*AST)
#define ATT_VHo (2*64*AST)
#define ATT_VLo (3*64*AST)
#define ATT_SMEM (ATT_S0 + 2*ATT_STAGE)   // 110592

__global__ __launch_bounds__(256, 1)
void attn_mma(const __nv_bfloat16* __restrict__ qh_g, const __nv_bfloat16* __restrict__ ql_g,
              const __nv_bfloat16* __restrict__ kh_g, const __nv_bfloat16* __restrict__ kl_g,
              const __nv_bfloat16* __restrict__ vh_g, const __nv_bfloat16* __restrict__ vl_g,
              __nv_bfloat16* __restrict__ oh_g, __nv_bfloat16* __restrict__ ol_g)
{
    extern __shared__ char smem[];
    const uint32_t sb = smem_u32(smem);
    const int tid = threadIdx.x, w = tid >> 5, lane = tid & 31;
    const int b = blockIdx.z, h = blockIdx.y, q0 = blockIdx.x * 128;
    const size_t tokbase = (size_t)(b*Ls + q0);
    const int coff = h * DHd;

    // load Q tiles (h/l), 128 rows x 128B
    #pragma unroll
    for (int it = 0; it < 4; it++) {
        const int unit = tid + it*256;
        const int r = unit >> 3, c = unit & 7;
        cp16(sb + ATT_QH + r*AST + c*16, qh_g + (tokbase + r)*Dd + coff + c*8);
        cp16(sb + ATT_QL + r*AST + c*16, ql_g + (tokbase + r)*Dd + coff + c*8);
    }
    asm volatile("cp.async.commit_group;" ::: "memory");

    auto load_kv = [&](int s, int t0) {
        const uint32_t st = sb + ATT_S0 + s*ATT_STAGE;
        const size_t kb = (size_t)(b*Ls + t0);
        #pragma unroll
        for (int it = 0; it < 2; it++) {
            const int unit = tid + it*256;
            const int r = unit >> 3, c = unit & 7;
            cp16(st + ATT_KHo + r*AST + c*16, kh_g + (kb + r)*Dd + coff + c*8);
            cp16(st + ATT_KLo + r*AST + c*16, kl_g + (kb + r)*Dd + coff + c*8);
            cp16(st + ATT_VHo + r*AST + c*16, vh_g + (kb + r)*Dd + coff + c*8);
            cp16(st + ATT_VLo + r*AST + c*16, vl_g + (kb + r)*Dd + coff + c*8);
        }
        asm volatile("cp.async.commit_group;" ::: "memory");
    };

    load_kv(0, 0);
    asm volatile("cp.async.wait_group 0;" ::: "memory");
    __syncthreads();

    // Q fragments in registers (A operand, m16 rows = w*16)
    uint32_t qhf[4][4], qlf[4][4];
    #pragma unroll
    for (int kc = 0; kc < 4; kc++) {
        const uint32_t ra = sb + ATT_QH + (w*16 + (lane & 15))*AST + kc*32 + ((lane >> 4) & 1)*16;
        ldsm4(qhf[kc], ra);
        ldsm4(qlf[kc], ra + ATT_QL);
    }

    float oacc[8][4];
    #pragma unroll
    for (int g = 0; g < 8; g++)
        #pragma unroll
        for (int i = 0; i < 4; i++) oacc[g][i] = 0.f;
    float m0 = -1e30f, m1 = -1e30f, l0 = 0.f, l1 = 0.f;

    for (int t = 0; t < Ls/64; t++) {
        if (t + 1 < Ls/64) {
            load_kv((t + 1) & 1, (t + 1) * 64);
            asm volatile("cp.async.wait_group 1;" ::: "memory");
        } else {
            asm volatile("cp.async.wait_group 0;" ::: "memory");
        }
        __syncthreads();
        const uint32_t st = sb + ATT_S0 + (t & 1)*ATT_STAGE;

        // ---- S = Q @ K^T (3-term split) ----
        float sc[8][4];
        #pragma unroll
        for (int g = 0; g < 8; g++)
            #pragma unroll
            for (int i = 0; i < 4; i++) sc[g][i] = 0.f;
        #pragma unroll
        for (int ng = 0; ng < 4; ng++) {
            #pragma unroll
            for (int kc = 0; kc < 4; kc++) {
                uint32_t bh[4], bl[4];
                const uint32_t rb = st + ATT_KHo + (ng*16 + (lane & 15))*AST + kc*32 + ((lane >> 4) & 1)*16;
                ldsm4(bh, rb);
                ldsm4(bl, rb + ATT_KLo);
                mma_bf16(sc[2*ng],   qhf[kc], bh[0], bh[2]);
                mma_bf16(sc[2*ng+1], qhf[kc], bh[1], bh[3]);
                mma_bf16(sc[2*ng],   qlf[kc], bh[0], bh[2]);
                mma_bf16(sc[2*ng+1], qlf[kc], bh[1], bh[3]);
                mma_bf16(sc[2*ng],   qhf[kc], bl[0], bl[2]);
                mma_bf16(sc[2*ng+1], qhf[kc], bl[1], bl[3]);
            }
        }

        // ---- online softmax (scale = 1/sqrt(H) = 0.25, faithful to source) ----
        float rm0 = -1e30f, rm1 = -1e30f;
        #pragma unroll
        for (int g = 0; g < 8; g++) {
            sc[g][0] *= 0.25f; sc[g][1] *= 0.25f; sc[g][2] *= 0.25f; sc[g][3] *= 0.25f;
            rm0 = fmaxf(rm0, fmaxf(sc[g][0], sc[g][1]));
            rm1 = fmaxf(rm1, fmaxf(sc[g][2], sc[g][3]));
        }
        rm0 = fmaxf(rm0, __shfl_xor_sync(0xffffffffu, rm0, 1));
        rm0 = fmaxf(rm0, __shfl_xor_sync(0xffffffffu, rm0, 2));
        rm1 = fmaxf(rm1, __shfl_xor_sync(0xffffffffu, rm1, 1));
        rm1 = fmaxf(rm1, __shfl_xor_sync(0xffffffffu, rm1, 2));
        const float nm0 = fmaxf(m0, rm0), nm1 = fmaxf(m1, rm1);
        const float c0 = __expf(m0 - nm0), c1 = __expf(m1 - nm1);
        m0 = nm0; m1 = nm1;

        float ls0 = 0.f, ls1 = 0.f;
        uint32_t phf[4][4], plf[4][4];
        #pragma unroll
        for (int g = 0; g < 8; g++) {
            const float p0 = __expf(sc[g][0] - m0);
            const float p1 = __expf(sc[g][1] - m0);
            const float p2 = __expf(sc[g][2] - m1);
            const float p3 = __expf(sc[g][3] - m1);
            ls0 += p0 + p1; ls1 += p2 + p3;
            const float ph0 = __bfloat162float(__float2bfloat16(p0));
            const float ph1 = __bfloat162float(__float2bfloat16(p1));
            const float ph2 = __bfloat162float(__float2bfloat16(p2));
            const float ph3 = __bfloat162float(__float2bfloat16(p3));
            const uint32_t hp01 = f2bf2(p0, p1), hp23 = f2bf2(p2, p3);
            const uint32_t lp01 = f2bf2(p0 - ph0, p1 - ph1), lp23 = f2bf2(p2 - ph2, p3 - ph3);
            const int kc = g >> 1;
            if ((g & 1) == 0) { phf[kc][0] = hp01; phf[kc][1] = hp23; plf[kc][0] = lp01; plf[kc][1] = lp23; }
            else              { phf[kc][2] = hp01; phf[kc][3] = hp23; plf[kc][2] = lp01; plf[kc][3] = lp23; }
            oacc[g][0] *= c0; oacc[g][1] *= c0; oacc[g][2] *= c1; oacc[g][3] *= c1;
        }
        ls0 += __shfl_xor_sync(0xffffffffu, ls0, 1);
        ls0 += __shfl_xor_sync(0xffffffffu, ls0, 2);
        ls1 += __shfl_xor_sync(0xffffffffu, ls1, 1);
        ls1 += __shfl_xor_sync(0xffffffffu, ls1, 2);
        l0 = l0*c0 + ls0; l1 = l1*c1 + ls1;

        // ---- O += P @ V (3-term split), V^T via ldmatrix.trans ----
        #pragma unroll
        for (int ng = 0; ng < 4; ng++) {
            #pragma unroll
            for (int kc = 0; kc < 4; kc++) {
                uint32_t vh[4], vl[4];
                const uint32_t rv = st + ATT_VHo + (kc*16 + (lane & 15))*AST + ng*32 + ((lane >> 4) & 1)*16;
                ldsm4t(vh, rv);
                ldsm4t(vl, rv + (ATT_VLo - ATT_VHo));
                mma_bf16(oacc[2*ng],   phf[kc], vh[0], vh[1]);
                mma_bf16(oacc[2*ng+1], phf[kc], vh[2], vh[3]);
                mma_bf16(oacc[2*ng],   plf[kc], vh[0], vh[1]);
                mma_bf16(oacc[2*ng+1], plf[kc], vh[2], vh[3]);
                mma_bf16(oacc[2*ng],   phf[kc], vl[0], vl[1]);
                mma_bf16(oacc[2*ng+1], phf[kc], vl[2], vl[3]);
            }
        }
        __syncthreads();
    }

    // ---- epilogue: normalize, split to bf16 hi/lo ----
    const float inv0 = 1.f / l0, inv1 = 1.f / l1;
    const size_t row0 = tokbase + w*16 + (lane >> 2);
    #pragma unroll
    for (int g = 0; g < 8; g++) {
        const int cc = coff + g*8 + (lane & 3)*2;
        const float o0 = oacc[g][0]*inv0, o1 = oacc[g][1]*inv0;
        const float o2 = oacc[g][2]*inv1, o3 = oacc[g][3]*inv1;
        const float h0 = __bfloat162float(__float2bfloat16(o0));
        const float h1 = __bfloat162float(__float2bfloat16(o1));
        const float h2 = __bfloat162float(__float2bfloat16(o2));
        const float h3 = __bfloat162float(__float2bfloat16(o3));
        *(uint32_t*)(oh_g + row0*Dd + cc)     = f2bf2(o0, o1);
        *(uint32_t*)(oh_g + (row0+8)*Dd + cc) = f2bf2(o2, o3);
        *(uint32_t*)(ol_g + row0*Dd + cc)     = f2bf2(o0 - h0, o1 - h1);
        *(uint32_t*)(ol_g + (row0+8)*Dd + cc) = f2bf2(o2 - h2, o3 - h3);
    }
}

// ---------------- host orchestration ----------------------------------------
extern "C" void kernel_launch(void* const* d_in, const int* in_sizes, int n_in,
                              void* d_out, int out_size)
{
    (void)in_sizes; (void)n_in; (void)out_size;
    const float* x  = (const float*)d_in[0];
    const float* wq = (const float*)d_in[1];
    const float* bq = (const float*)d_in[2];
    const float* wk = (const float*)d_in[3];
    const float* bk = (const float*)d_in[4];
    const float* wv = (const float*)d_in[5];
    const float* bv = (const float*)d_in[6];
    const float* wo = (const float*)d_in[7];
    const float* bo = (const float*)d_in[8];
    const float* w1 = (const float*)d_in[9];
    const float* b1 = (const float*)d_in[10];
    const float* w2 = (const float*)d_in[11];
    const float* b2 = (const float*)d_in[12];
    float* out = (float*)d_out;

    float *r1;
    cudaGetSymbolAddress((void**)&r1, g_r1);

    __nv_bfloat16 *wqh,*wql,*wkh,*wkl,*wvh,*wvl,*woh,*wol,*w1h,*w1l,*w2h,*w2l;
    __nv_bfloat16 *hh,*hl,*yh,*yl,*oh,*ol,*fh,*fl;
    __nv_bfloat16 *qh,*ql,*kh,*kl,*vh,*vl;
    cudaGetSymbolAddress((void**)&wqh, g_wqh); cudaGetSymbolAddress((void**)&wql, g_wql);
    cudaGetSymbolAddress((void**)&wkh, g_wkh); cudaGetSymbolAddress((void**)&wkl, g_wkl);
    cudaGetSymbolAddress((void**)&wvh, g_wvh); cudaGetSymbolAddress((void**)&wvl, g_wvl);
    cudaGetSymbolAddress((void**)&woh, g_woh); cudaGetSymbolAddress((void**)&wol, g_wol);
    cudaGetSymbolAddress((void**)&w1h, g_w1h); cudaGetSymbolAddress((void**)&w1l, g_w1l);
    cudaGetSymbolAddress((void**)&w2h, g_w2h); cudaGetSymbolAddress((void**)&w2l, g_w2l);
    cudaGetSymbolAddress((void**)&hh,  g_hh);  cudaGetSymbolAddress((void**)&hl,  g_hl);
    cudaGetSymbolAddress((void**)&yh,  g_yh);  cudaGetSymbolAddress((void**)&yl,  g_yl);
    cudaGetSymbolAddress((void**)&oh,  g_oh);  cudaGetSymbolAddress((void**)&ol,  g_ol);
    cudaGetSymbolAddress((void**)&fh,  g_fh);  cudaGetSymbolAddress((void**)&fl,  g_fl);
    cudaGetSymbolAddress((void**)&qh,  g_qh);  cudaGetSymbolAddress((void**)&ql,  g_ql);
    cudaGetSymbolAddress((void**)&kh,  g_kh);  cudaGetSymbolAddress((void**)&kl,  g_kl);
    cudaGetSymbolAddress((void**)&vh,  g_vh);  cudaGetSymbolAddress((void**)&vl,  g_vl);

    cudaFuncSetAttribute(gemm_mma<false,false,false>, cudaFuncAttributeMaxDynamicSharedMemorySize, GEMM_SMEM);
    cudaFuncSetAttribute(gemm_mma<false,true, false>, cudaFuncAttributeMaxDynamicSharedMemorySize, GEMM_SMEM);
    cudaFuncSetAttribute(gemm_mma<true, false,true >, cudaFuncAttributeMaxDynamicSharedMemorySize, GEMM_SMEM);
    cudaFuncSetAttribute(gemm_mma<false,false,true >, cudaFuncAttributeMaxDynamicSharedMemorySize, GEMM_SMEM);
    cudaFuncSetAttribute(attn_mma, cudaFuncAttributeMaxDynamicSharedMemorySize, ATT_SMEM);

    const dim3 gProj(Dd/128, Mrows/128);     // (8, 32)
    const dim3 gFF1(FFd/128, Mrows/128);     // (32, 32)

    // weight splits
    split_kernel<<<(Dd*Dd)/1024, 256>>>(wq, wqh, wql);
    split_kernel<<<(Dd*Dd)/1024, 256>>>(wk, wkh, wkl);
    split_kernel<<<(Dd*Dd)/1024, 256>>>(wv, wvh, wvl);
    split_kernel<<<(Dd*Dd)/1024, 256>>>(wo, woh, wol);
    split_kernel<<<(FFd*Dd)/1024, 256>>>(w1, w1h, w1l);
    split_kernel<<<(Dd*FFd)/1024, 256>>>(w2, w2h, w2l);

    // LN1 -> h (hi/lo)
    ln_partial<<<dim3(NPART, Bb), 256>>>(x);
    ln_final<<<Bb, 32>>>();
    ln_apply_split<<<(Mrows*Dd)/4/256, 256>>>(x, hh, hl);

    // QKV projections -> split bf16 directly
    gemm_mma<false,false,true><<<gProj, 256, GEMM_SMEM>>>(hh, hl, wqh, wql, bq, nullptr, nullptr, qh, ql, Dd, Dd);
    gemm_mma<false,false,true><<<gProj, 256, GEMM_SMEM>>>(hh, hl, wkh, wkl, bk, nullptr, nullptr, kh, kl, Dd, Dd);
    gemm_mma<false,false,true><<<gProj, 256, GEMM_SMEM>>>(hh, hl, wvh, wvl, bv, nullptr, nullptr, vh, vl, Dd, Dd);

    // attention (MMA) -> split bf16 o
    attn_mma<<<dim3(Ls/128, Hh, Bb), 256, ATT_SMEM>>>(qh, ql, kh, kl, vh, vl, oh, ol);

    // out-proj + residual(x)
    gemm_mma<false,true,false><<<gProj, 256, GEMM_SMEM>>>(oh, ol, woh, wol, bo, x, r1, nullptr, nullptr, Dd, Dd);

    // LN2 -> y (hi/lo)
    ln_partial<<<dim3(NPART, Bb), 256>>>(r1);
    ln_final<<<Bb, 32>>>();
    ln_apply_split<<<(Mrows*Dd)/4/256, 256>>>(r1, yh, yl);

    // FFN1: relu, emit bf16 hi/lo directly
    gemm_mma<true,false,true><<<gFF1, 256, GEMM_SMEM>>>(yh, yl, w1h, w1l, b1, nullptr, nullptr, fh, fl, FFd, Dd);
    // FFN2: + residual(x), fp32 out
    gemm_mma<false,true,false><<<gProj, 256, GEMM_SMEM>>>(fh, fl, w2h, w2l, b2, x, out, nullptr, nullptr, Dd, FFd);
}

// round 10
// speedup vs baseline: 5.3549x; 1.4265x over previous
#include <cuda_runtime.h>
#include <cuda_fp16.h>
#include <math.h>
#include <stdint.h>

// Problem constants
#define Bb   2
#define Ls   2048
#define Dd   1024
#define Hh   16
#define DHd  64
#define FFd  4096
#define Mrows (Bb*Ls)      // 4096
#define LD    (Ls*Dd)      // 2097152
#define NPART 64

// ---------------- scratch (static device globals; no allocation) -------------
__device__ float g_r1[Mrows*Dd];
__device__ float g_part[Bb*NPART*2];
__device__ float g_stats[Bb*2];

// fp16 buffers (weights split hi/lo; activations single, except Q)
__device__ __align__(256) __half g_wqh[Dd*Dd],  g_wql[Dd*Dd];
__device__ __align__(256) __half g_wkh[Dd*Dd],  g_wkl[Dd*Dd];
__device__ __align__(256) __half g_wvh[Dd*Dd],  g_wvl[Dd*Dd];
__device__ __align__(256) __half g_woh[Dd*Dd],  g_wol[Dd*Dd];
__device__ __align__(256) __half g_w1h[FFd*Dd], g_w1l[FFd*Dd];
__device__ __align__(256) __half g_w2h[Dd*FFd], g_w2l[Dd*FFd];
__device__ __align__(256) __half g_h[Mrows*Dd];
__device__ __align__(256) __half g_y[Mrows*Dd];
__device__ __align__(256) __half g_f[Mrows*FFd];
__device__ __align__(256) __half g_oH[Mrows*Dd];
__device__ __align__(256) __half g_qh[Mrows*Dd], g_ql[Mrows*Dd];
__device__ __align__(256) __half g_kh[Mrows*Dd];
__device__ __align__(256) __half g_vh[Mrows*Dd];

// ---------------- PTX helpers (all legal on plain sm_103) ---------------------
__device__ __forceinline__ uint32_t smem_u32(const void* p) {
    uint32_t a;
    asm("{ .reg .u64 t; cvta.to.shared.u64 t, %1; cvt.u32.u64 %0, t; }" : "=r"(a) : "l"(p));
    return a;
}
__device__ __forceinline__ void cp16(uint32_t dst, const void* src) {
    asm volatile("cp.async.cg.shared.global [%0], [%1], 16;" :: "r"(dst), "l"(src) : "memory");
}
__device__ __forceinline__ void ldsm4(uint32_t* r, uint32_t addr) {
    asm volatile("ldmatrix.sync.aligned.m8n8.x4.shared.b16 {%0,%1,%2,%3}, [%4];"
                 : "=r"(r[0]), "=r"(r[1]), "=r"(r[2]), "=r"(r[3]) : "r"(addr));
}
__device__ __forceinline__ void ldsm4t(uint32_t* r, uint32_t addr) {
    asm volatile("ldmatrix.sync.aligned.m8n8.x4.trans.shared.b16 {%0,%1,%2,%3}, [%4];"
                 : "=r"(r[0]), "=r"(r[1]), "=r"(r[2]), "=r"(r[3]) : "r"(addr));
}
__device__ __forceinline__ void mma_f16(float* c, const uint32_t* a, uint32_t b0, uint32_t b1) {
    asm volatile(
        "mma.sync.aligned.m16n8k16.row.col.f32.f16.f16.f32 "
        "{%0,%1,%2,%3}, {%4,%5,%6,%7}, {%8,%9}, {%0,%1,%2,%3};"
        : "+f"(c[0]), "+f"(c[1]), "+f"(c[2]), "+f"(c[3])
        : "r"(a[0]), "r"(a[1]), "r"(a[2]), "r"(a[3]), "r"(b0), "r"(b1));
}
__device__ __forceinline__ uint32_t f2h2(float lo, float hi) {
    __half2 t = __floats2half2_rn(lo, hi);
    return *reinterpret_cast<uint32_t*>(&t);
}

// ---------------- fp32 -> fp16 hi/lo split (weights) --------------------------
__global__ void split_kernel(const float* __restrict__ in,
                             __half* __restrict__ hi, __half* __restrict__ lo) {
    const int idx = blockIdx.x * 256 + threadIdx.x;    // float4 index
    float4 v = ((const float4*)in)[idx];
    float h0 = __half2float(__float2half_rn(v.x));
    float h1 = __half2float(__float2half_rn(v.y));
    float h2 = __half2float(__float2half_rn(v.z));
    float h3 = __half2float(__float2half_rn(v.w));
    ((uint32_t*)hi)[2*idx]   = f2h2(v.x, v.y);
    ((uint32_t*)hi)[2*idx+1] = f2h2(v.z, v.w);
    ((uint32_t*)lo)[2*idx]   = f2h2(v.x - h0, v.y - h1);
    ((uint32_t*)lo)[2*idx+1] = f2h2(v.z - h2, v.w - h3);
}

// ---------------- LayerNorm over (L,D) jointly per batch ---------------------
__global__ void ln_partial(const float* __restrict__ x) {
    const int b = blockIdx.y;
    const int tid = threadIdx.x;
    const int chunk4 = (LD / NPART) / 4;
    const float4* xp = (const float4*)(x + (size_t)b * LD) + (size_t)blockIdx.x * chunk4;
    float s = 0.f, s2 = 0.f;
    for (int i = tid; i < chunk4; i += 256) {
        float4 v = xp[i];
        s  += v.x + v.y + v.z + v.w;
        s2 += v.x*v.x + v.y*v.y + v.z*v.z + v.w*v.w;
    }
    __shared__ float sh[2][256];
    sh[0][tid] = s; sh[1][tid] = s2;
    __syncthreads();
    for (int st = 128; st > 0; st >>= 1) {
        if (tid < st) { sh[0][tid] += sh[0][tid+st]; sh[1][tid] += sh[1][tid+st]; }
        __syncthreads();
    }
    if (tid == 0) {
        g_part[(b*NPART + blockIdx.x)*2 + 0] = sh[0][0];
        g_part[(b*NPART + blockIdx.x)*2 + 1] = sh[1][0];
    }
}

__global__ void ln_final() {
    const int b = blockIdx.x, t = threadIdx.x;   // 32 threads
    float s  = g_part[(b*NPART + t)*2 + 0] + g_part[(b*NPART + t + 32)*2 + 0];
    float s2 = g_part[(b*NPART + t)*2 + 1] + g_part[(b*NPART + t + 32)*2 + 1];
    for (int o = 16; o; o >>= 1) {
        s  += __shfl_xor_sync(0xffffffffu, s,  o);
        s2 += __shfl_xor_sync(0xffffffffu, s2, o);
    }
    if (t == 0) {
        float mu  = s / (float)LD;
        float var = s2 / (float)LD - mu*mu;
        g_stats[b*2 + 0] = mu;
        g_stats[b*2 + 1] = rsqrtf(var + 1e-5f);
    }
}

// normalize, emit single fp16
__global__ void ln_apply_h(const float* __restrict__ in, __half* __restrict__ outp) {
    const int idx = blockIdx.x * blockDim.x + threadIdx.x;   // float4 index
    const int b = idx / (LD/4);
    const float mu = g_stats[b*2 + 0], rs = g_stats[b*2 + 1];
    float4 v = ((const float4*)in)[idx];
    ((uint32_t*)outp)[2*idx]   = f2h2((v.x - mu)*rs, (v.y - mu)*rs);
    ((uint32_t*)outp)[2*idx+1] = f2h2((v.z - mu)*rs, (v.w - mu)*rs);
}

// ---------------- mma.sync 2-term fp16 GEMM -----------------------------------
// C[M,N] = A[M,K] @ (Wh + Wl)[N,K]^T, fp32 accum.
// 128x128 CTA tile, BK=32, 3-stage cp.async pipeline.
// Per stage 3 tiles (A, Wh, Wl), each 128 rows x 32 fp16, row stride 80B.
#define TILE_B   10240              // 128 * 80
#define STAGE_B  (3*TILE_B)         // 30720
#define GEMM_SMEM (3*STAGE_B)       // 92160

// OUT: 0 = fp32 C, 1 = single fp16 Ch, 2 = split fp16 Ch/Cl
template<bool RELU, bool RESID, int OUT>
__global__ __launch_bounds__(256)
void gemm_mma(const __half* __restrict__ A,
              const __half* __restrict__ Wh, const __half* __restrict__ Wl,
              const float* __restrict__ bias, const float* __restrict__ R,
              float* __restrict__ C,
              __half* __restrict__ Ch, __half* __restrict__ Cl,
              int Ndim, int Kdim)
{
    extern __shared__ char smem[];
    const uint32_t sb = smem_u32(smem);
    const int tid  = threadIdx.x;
    const int wid  = tid >> 5, lane = tid & 31;
    const int wm   = wid & 3;
    const int wn   = wid >> 2;
    const int bm   = blockIdx.y * 128, bn = blockIdx.x * 128;

    float acc[2][8][4];
    #pragma unroll
    for (int i = 0; i < 2; i++)
        #pragma unroll
        for (int j = 0; j < 8; j++)
            #pragma unroll
            for (int t = 0; t < 4; t++) acc[i][j][t] = 0.f;

    const int r0c = tid >> 2, c0c = tid & 3;
    const int r1c = (tid + 256) >> 2, c1c = tid & 3;

    auto load_stage = [&](int s, int k0) {
        const uint32_t st = sb + s * STAGE_B;
        cp16(st + 0*TILE_B + r0c*80 + c0c*16, A  + (size_t)(bm + r0c)*Kdim + k0 + c0c*8);
        cp16(st + 0*TILE_B + r1c*80 + c1c*16, A  + (size_t)(bm + r1c)*Kdim + k0 + c1c*8);
        cp16(st + 1*TILE_B + r0c*80 + c0c*16, Wh + (size_t)(bn + r0c)*Kdim + k0 + c0c*8);
        cp16(st + 1*TILE_B + r1c*80 + c1c*16, Wh + (size_t)(bn + r1c)*Kdim + k0 + c1c*8);
        cp16(st + 2*TILE_B + r0c*80 + c0c*16, Wl + (size_t)(bn + r0c)*Kdim + k0 + c0c*8);
        cp16(st + 2*TILE_B + r1c*80 + c1c*16, Wl + (size_t)(bn + r1c)*Kdim + k0 + c1c*8);
        asm volatile("cp.async.commit_group;" ::: "memory");
    };

    const int nk = Kdim >> 5;
    load_stage(0, 0);
    load_stage(1, 32);

    for (int kt = 0; kt < nk; kt++) {
        if (kt + 1 < nk) { asm volatile("cp.async.wait_group 1;" ::: "memory"); }
        else             { asm volatile("cp.async.wait_group 0;" ::: "memory"); }
        __syncthreads();
        if (kt + 2 < nk) load_stage((kt + 2) % 3, (kt + 2) << 5);

        const uint32_t st = sb + (kt % 3) * STAGE_B;
        #pragma unroll
        for (int ks = 0; ks < 2; ks++) {
            const uint32_t koff = ks*32 + ((lane >> 4) & 1)*16;
            uint32_t a[2][4];
            #pragma unroll
            for (int mt = 0; mt < 2; mt++)
                ldsm4(a[mt], st + (wm*32 + mt*16 + (lane & 15))*80 + koff);
            #pragma unroll
            for (int g = 0; g < 4; g++) {
                const uint32_t rb = st + TILE_B + (wn*64 + g*16 + (lane & 15))*80 + koff;
                uint32_t wh[4], wl[4];
                ldsm4(wh, rb);
                ldsm4(wl, rb + TILE_B);
                #pragma unroll
                for (int mt = 0; mt < 2; mt++) {
                    float* cA = acc[mt][2*g];
                    float* cB = acc[mt][2*g+1];
                    mma_f16(cA, a[mt], wh[0], wh[2]);
                    mma_f16(cB, a[mt], wh[1], wh[3]);
                    mma_f16(cA, a[mt], wl[0], wl[2]);
                    mma_f16(cB, a[mt], wl[1], wl[3]);
                }
            }
        }
    }

    // ---- epilogue ----
    #pragma unroll
    for (int mt = 0; mt < 2; mt++) {
        const int row0 = bm + wm*32 + mt*16 + (lane >> 2);
        #pragma unroll
        for (int nt = 0; nt < 8; nt++) {
            const int cc = bn + wn*64 + nt*8 + (lane & 3)*2;
            const float b0 = bias[cc], b1 = bias[cc+1];
            float v00 = acc[mt][nt][0] + b0, v01 = acc[mt][nt][1] + b1;
            float v10 = acc[mt][nt][2] + b0, v11 = acc[mt][nt][3] + b1;
            if (RESID) {
                v00 += R[(size_t)row0*Ndim + cc];     v01 += R[(size_t)row0*Ndim + cc + 1];
                v10 += R[(size_t)(row0+8)*Ndim + cc]; v11 += R[(size_t)(row0+8)*Ndim + cc + 1];
            }
            if (RELU) {
                v00 = fmaxf(v00, 0.f); v01 = fmaxf(v01, 0.f);
                v10 = fmaxf(v10, 0.f); v11 = fmaxf(v11, 0.f);
            }
            if (OUT == 0) {
                *(float2*)(C + (size_t)row0*Ndim + cc)     = {v00, v01};
                *(float2*)(C + (size_t)(row0+8)*Ndim + cc) = {v10, v11};
            } else if (OUT == 1) {
                *(uint32_t*)(Ch + (size_t)row0*Ndim + cc)     = f2h2(v00, v01);
                *(uint32_t*)(Ch + (size_t)(row0+8)*Ndim + cc) = f2h2(v10, v11);
            } else {
                const float h00 = __half2float(__float2half_rn(v00));
                const float h01 = __half2float(__float2half_rn(v01));
                const float h10 = __half2float(__float2half_rn(v10));
                const float h11 = __half2float(__float2half_rn(v11));
                *(uint32_t*)(Ch + (size_t)row0*Ndim + cc)     = f2h2(v00, v01);
                *(uint32_t*)(Ch + (size_t)(row0+8)*Ndim + cc) = f2h2(v10, v11);
                *(uint32_t*)(Cl + (size_t)row0*Ndim + cc)     = f2h2(v00 - h00, v01 - h01);
                *(uint32_t*)(Cl + (size_t)(row0+8)*Ndim + cc) = f2h2(v10 - h10, v11 - h11);
            }
        }
    }
}

// ---------------- MMA flash attention (fp16, Q/P split; K/V single) -----------
// Per CTA: one (b, h), 128 q rows. 8 warps x 16 q rows.
// KV streamed in 64-key chunks, 3-stage cp.async.
// S = Qh*K + Ql*K ; O += Ph*V + Pl*V ; fp32 softmax.
#define AST 144                      // smem row stride bytes (64 fp16 + 16B pad)
#define ATT_QH 0
#define ATT_QL (128*AST)             // 18432
#define ATT_S0 (2*128*AST)           // 36864
#define ATT_STAGE (2*64*AST)         // 18432 (K tile + V tile)
#define ATT_Vo (64*AST)
#define ATT_SMEM (ATT_S0 + 3*ATT_STAGE)   // 92160

__global__ __launch_bounds__(256, 1)
void attn_mma(const __half* __restrict__ qh_g, const __half* __restrict__ ql_g,
              const __half* __restrict__ kh_g, const __half* __restrict__ vh_g,
              __half* __restrict__ o_g)
{
    extern __shared__ char smem[];
    const uint32_t sb = smem_u32(smem);
    const int tid = threadIdx.x, w = tid >> 5, lane = tid & 31;
    const int b = blockIdx.z, h = blockIdx.y, q0 = blockIdx.x * 128;
    const size_t tokbase = (size_t)(b*Ls + q0);
    const int coff = h * DHd;

    // load Q tiles (h/l), 128 rows x 128B
    #pragma unroll
    for (int it = 0; it < 4; it++) {
        const int unit = tid + it*256;
        const int r = unit >> 3, c = unit & 7;
        cp16(sb + ATT_QH + r*AST + c*16, qh_g + (tokbase + r)*Dd + coff + c*8);
        cp16(sb + ATT_QL + r*AST + c*16, ql_g + (tokbase + r)*Dd + coff + c*8);
    }
    asm volatile("cp.async.commit_group;" ::: "memory");

    auto load_kv = [&](int s, int t0) {
        const uint32_t st = sb + ATT_S0 + s*ATT_STAGE;
        const size_t kb = (size_t)(b*Ls + t0);
        #pragma unroll
        for (int it = 0; it < 2; it++) {
            const int unit = tid + it*256;
            const int r = unit >> 3, c = unit & 7;
            cp16(st + r*AST + c*16,          kh_g + (kb + r)*Dd + coff + c*8);
            cp16(st + ATT_Vo + r*AST + c*16, vh_g + (kb + r)*Dd + coff + c*8);
        }
        asm volatile("cp.async.commit_group;" ::: "memory");
    };

    load_kv(0, 0);
    load_kv(1, 64);
    asm volatile("cp.async.wait_group 1;" ::: "memory");   // Q + kv0 ready
    __syncthreads();

    // Q fragments in registers (A operand, m16 rows = w*16)
    uint32_t qhf[4][4], qlf[4][4];
    #pragma unroll
    for (int kc = 0; kc < 4; kc++) {
        const uint32_t ra = sb + ATT_QH + (w*16 + (lane & 15))*AST + kc*32 + ((lane >> 4) & 1)*16;
        ldsm4(qhf[kc], ra);
        ldsm4(qlf[kc], ra + ATT_QL);
    }

    float oacc[8][4];
    #pragma unroll
    for (int g = 0; g < 8; g++)
        #pragma unroll
        for (int i = 0; i < 4; i++) oacc[g][i] = 0.f;
    float m0 = -1e30f, m1 = -1e30f, l0 = 0.f, l1 = 0.f;

    const int nt = Ls/64;
    for (int t = 0; t < nt; t++) {
        if (t > 0) {
            if (t + 1 < nt) { asm volatile("cp.async.wait_group 1;" ::: "memory"); }
            else            { asm volatile("cp.async.wait_group 0;" ::: "memory"); }
            __syncthreads();
        }
        if (t + 2 < nt) load_kv((t + 2) % 3, (t + 2) * 64);
        const uint32_t st = sb + ATT_S0 + (t % 3)*ATT_STAGE;

        // ---- S = Q @ K^T (2-term: Qh + Ql) ----
        float sc[8][4];
        #pragma unroll
        for (int g = 0; g < 8; g++)
            #pragma unroll
            for (int i = 0; i < 4; i++) sc[g][i] = 0.f;
        #pragma unroll
        for (int ng = 0; ng < 4; ng++) {
            #pragma unroll
            for (int kc = 0; kc < 4; kc++) {
                uint32_t bh[4];
                const uint32_t rb = st + (ng*16 + (lane & 15))*AST + kc*32 + ((lane >> 4) & 1)*16;
                ldsm4(bh, rb);
                mma_f16(sc[2*ng],   qhf[kc], bh[0], bh[2]);
                mma_f16(sc[2*ng+1], qhf[kc], bh[1], bh[3]);
                mma_f16(sc[2*ng],   qlf[kc], bh[0], bh[2]);
                mma_f16(sc[2*ng+1], qlf[kc], bh[1], bh[3]);
            }
        }

        // ---- online softmax (scale = 1/sqrt(H) = 0.25, faithful to source) ----
        float rm0 = -1e30f, rm1 = -1e30f;
        #pragma unroll
        for (int g = 0; g < 8; g++) {
            sc[g][0] *= 0.25f; sc[g][1] *= 0.25f; sc[g][2] *= 0.25f; sc[g][3] *= 0.25f;
            rm0 = fmaxf(rm0, fmaxf(sc[g][0], sc[g][1]));
            rm1 = fmaxf(rm1, fmaxf(sc[g][2], sc[g][3]));
        }
        rm0 = fmaxf(rm0, __shfl_xor_sync(0xffffffffu, rm0, 1));
        rm0 = fmaxf(rm0, __shfl_xor_sync(0xffffffffu, rm0, 2));
        rm1 = fmaxf(rm1, __shfl_xor_sync(0xffffffffu, rm1, 1));
        rm1 = fmaxf(rm1, __shfl_xor_sync(0xffffffffu, rm1, 2));
        const float nm0 = fmaxf(m0, rm0), nm1 = fmaxf(m1, rm1);
        const float c0 = __expf(m0 - nm0), c1 = __expf(m1 - nm1);
        m0 = nm0; m1 = nm1;

        float ls0 = 0.f, ls1 = 0.f;
        uint32_t phf[4][4], plf[4][4];
        #pragma unroll
        for (int g = 0; g < 8; g++) {
            const float p0 = __expf(sc[g][0] - m0);
            const float p1 = __expf(sc[g][1] - m0);
            const float p2 = __expf(sc[g][2] - m1);
            const float p3 = __expf(sc[g][3] - m1);
            ls0 += p0 + p1; ls1 += p2 + p3;
            const float ph0 = __half2float(__float2half_rn(p0));
            const float ph1 = __half2float(__float2half_rn(p1));
            const float ph2 = __half2float(__float2half_rn(p2));
            const float ph3 = __half2float(__float2half_rn(p3));
            const uint32_t hp01 = f2h2(p0, p1), hp23 = f2h2(p2, p3);
            const uint32_t lp01 = f2h2(p0 - ph0, p1 - ph1), lp23 = f2h2(p2 - ph2, p3 - ph3);
            const int kc = g >> 1;
            if ((g & 1) == 0) { phf[kc][0] = hp01; phf[kc][1] = hp23; plf[kc][0] = lp01; plf[kc][1] = lp23; }
            else              { phf[kc][2] = hp01; phf[kc][3] = hp23; plf[kc][2] = lp01; plf[kc][3] = lp23; }
            oacc[g][0] *= c0; oacc[g][1] *= c0; oacc[g][2] *= c1; oacc[g][3] *= c1;
        }
        ls0 += __shfl_xor_sync(0xffffffffu, ls0, 1);
        ls0 += __shfl_xor_sync(0xffffffffu, ls0, 2);
        ls1 += __shfl_xor_sync(0xffffffffu, ls1, 1);
        ls1 += __shfl_xor_sync(0xffffffffu, ls1, 2);
        l0 = l0*c0 + ls0; l1 = l1*c1 + ls1;

        // ---- O += P @ V (2-term: Ph + Pl), V^T via ldmatrix.trans ----
        #pragma unroll
        for (int ng = 0; ng < 4; ng++) {
            #pragma unroll
            for (int kc = 0; kc < 4; kc++) {
                uint32_t vv[4];
                const uint32_t rv = st + ATT_Vo + (kc*16 + (lane & 15))*AST + ng*32 + ((lane >> 4) & 1)*16;
                ldsm4t(vv, rv);
                mma_f16(oacc[2*ng],   phf[kc], vv[0], vv[1]);
                mma_f16(oacc[2*ng+1], phf[kc], vv[2], vv[3]);
                mma_f16(oacc[2*ng],   plf[kc], vv[0], vv[1]);
                mma_f16(oacc[2*ng+1], plf[kc], vv[2], vv[3]);
            }
        }
    }

    // ---- epilogue: normalize, single fp16 out ----
    const float inv0 = 1.f / l0, inv1 = 1.f / l1;
    const size_t row0 = tokbase + w*16 + (lane >> 2);
    #pragma unroll
    for (int g = 0; g < 8; g++) {
        const int cc = coff + g*8 + (lane & 3)*2;
        *(uint32_t*)(o_g + row0*Dd + cc)     = f2h2(oacc[g][0]*inv0, oacc[g][1]*inv0);
        *(uint32_t*)(o_g + (row0+8)*Dd + cc) = f2h2(oacc[g][2]*inv1, oacc[g][3]*inv1);
    }
}

// ---------------- host orchestration ----------------------------------------
extern "C" void kernel_launch(void* const* d_in, const int* in_sizes, int n_in,
                              void* d_out, int out_size)
{
    (void)in_sizes; (void)n_in; (void)out_size;
    const float* x  = (const float*)d_in[0];
    const float* wq = (const float*)d_in[1];
    const float* bq = (const float*)d_in[2];
    const float* wk = (const float*)d_in[3];
    const float* bk = (const float*)d_in[4];
    const float* wv = (const float*)d_in[5];
    const float* bv = (const float*)d_in[6];
    const float* wo = (const float*)d_in[7];
    const float* bo = (const float*)d_in[8];
    const float* w1 = (const float*)d_in[9];
    const float* b1 = (const float*)d_in[10];
    const float* w2 = (const float*)d_in[11];
    const float* b2 = (const float*)d_in[12];
    float* out = (float*)d_out;

    float *r1;
    cudaGetSymbolAddress((void**)&r1, g_r1);

    __half *wqh,*wql,*wkh,*wkl,*wvh,*wvl,*woh,*wol,*w1h,*w1l,*w2h,*w2l;
    __half *hA,*yA,*fA,*oA,*qh,*ql,*kh,*vh;
    cudaGetSymbolAddress((void**)&wqh, g_wqh); cudaGetSymbolAddress((void**)&wql, g_wql);
    cudaGetSymbolAddress((void**)&wkh, g_wkh); cudaGetSymbolAddress((void**)&wkl, g_wkl);
    cudaGetSymbolAddress((void**)&wvh, g_wvh); cudaGetSymbolAddress((void**)&wvl, g_wvl);
    cudaGetSymbolAddress((void**)&woh, g_woh); cudaGetSymbolAddress((void**)&wol, g_wol);
    cudaGetSymbolAddress((void**)&w1h, g_w1h); cudaGetSymbolAddress((void**)&w1l, g_w1l);
    cudaGetSymbolAddress((void**)&w2h, g_w2h); cudaGetSymbolAddress((void**)&w2l, g_w2l);
    cudaGetSymbolAddress((void**)&hA,  g_h);   cudaGetSymbolAddress((void**)&yA,  g_y);
    cudaGetSymbolAddress((void**)&fA,  g_f);   cudaGetSymbolAddress((void**)&oA,  g_oH);
    cudaGetSymbolAddress((void**)&qh,  g_qh);  cudaGetSymbolAddress((void**)&ql,  g_ql);
    cudaGetSymbolAddress((void**)&kh,  g_kh);  cudaGetSymbolAddress((void**)&vh,  g_vh);

    cudaFuncSetAttribute(gemm_mma<false,false,2>, cudaFuncAttributeMaxDynamicSharedMemorySize, GEMM_SMEM);
    cudaFuncSetAttribute(gemm_mma<false,false,1>, cudaFuncAttributeMaxDynamicSharedMemorySize, GEMM_SMEM);
    cudaFuncSetAttribute(gemm_mma<false,true, 0>, cudaFuncAttributeMaxDynamicSharedMemorySize, GEMM_SMEM);
    cudaFuncSetAttribute(gemm_mma<true, false,1>, cudaFuncAttributeMaxDynamicSharedMemorySize, GEMM_SMEM);
    cudaFuncSetAttribute(attn_mma, cudaFuncAttributeMaxDynamicSharedMemorySize, ATT_SMEM);

    const dim3 gProj(Dd/128, Mrows/128);     // (8, 32)
    const dim3 gFF1(FFd/128, Mrows/128);     // (32, 32)

    // weight splits
    split_kernel<<<(Dd*Dd)/1024, 256>>>(wq, wqh, wql);
    split_kernel<<<(Dd*Dd)/1024, 256>>>(wk, wkh, wkl);
    split_kernel<<<(Dd*Dd)/1024, 256>>>(wv, wvh, wvl);
    split_kernel<<<(Dd*Dd)/1024, 256>>>(wo, woh, wol);
    split_kernel<<<(FFd*Dd)/1024, 256>>>(w1, w1h, w1l);
    split_kernel<<<(Dd*FFd)/1024, 256>>>(w2, w2h, w2l);

    // LN1 -> h (single fp16)
    ln_partial<<<dim3(NPART, Bb), 256>>>(x);
    ln_final<<<Bb, 32>>>();
    ln_apply_h<<<(Mrows*Dd)/4/256, 256>>>(x, hA);

    // QKV projections: Q split, K/V single
    gemm_mma<false,false,2><<<gProj, 256, GEMM_SMEM>>>(hA, wqh, wql, bq, nullptr, nullptr, qh, ql, Dd, Dd);
    gemm_mma<false,false,1><<<gProj, 256, GEMM_SMEM>>>(hA, wkh, wkl, bk, nullptr, nullptr, kh, nullptr, Dd, Dd);
    gemm_mma<false,false,1><<<gProj, 256, GEMM_SMEM>>>(hA, wvh, wvl, bv, nullptr, nullptr, vh, nullptr, Dd, Dd);

    // attention (MMA) -> single fp16 o
    attn_mma<<<dim3(Ls/128, Hh, Bb), 256, ATT_SMEM>>>(qh, ql, kh, vh, oA);

    // out-proj + residual(x) -> fp32 r1
    gemm_mma<false,true,0><<<gProj, 256, GEMM_SMEM>>>(oA, woh, wol, bo, x, r1, nullptr, nullptr, Dd, Dd);

    // LN2 -> y (single fp16)
    ln_partial<<<dim3(NPART, Bb), 256>>>(r1);
    ln_final<<<Bb, 32>>>();
    ln_apply_h<<<(Mrows*Dd)/4/256, 256>>>(r1, yA);

    // FFN1: relu, single fp16 f
    gemm_mma<true,false,1><<<gFF1, 256, GEMM_SMEM>>>(yA, w1h, w1l, b1, nullptr, nullptr, fA, nullptr, FFd, Dd);
    // FFN2: + residual(x), fp32 out
    gemm_mma<false,true,0><<<gProj, 256, GEMM_SMEM>>>(fA, w2h, w2l, b2, x, out, nullptr, nullptr, Dd, FFd);
}

// round 11
// speedup vs baseline: 8.6194x; 1.6096x over previous
#include <cuda_runtime.h>
#include <cuda_fp16.h>
#include <math.h>
#include <stdint.h>

// Problem constants
#define Bb   2
#define Ls   2048
#define Dd   1024
#define Hh   16
#define DHd  64
#define FFd  4096
#define Mrows (Bb*Ls)      // 4096
#define LD    (Ls*Dd)      // 2097152
#define NPART 64

// ---------------- scratch (static device globals; no allocation) -------------
__device__ float g_r1[Mrows*Dd];
__device__ float g_part[Bb*NPART*2];
__device__ float g_stats[Bb*2];

// fp16 buffers (all single-precision fp16; error budget verified empirically)
__device__ __align__(256) __half g_wq[Dd*Dd];
__device__ __align__(256) __half g_wk[Dd*Dd];
__device__ __align__(256) __half g_wv[Dd*Dd];
__device__ __align__(256) __half g_wo[Dd*Dd];
__device__ __align__(256) __half g_w1[FFd*Dd];
__device__ __align__(256) __half g_w2[Dd*FFd];
__device__ __align__(256) __half g_h[Mrows*Dd];
__device__ __align__(256) __half g_y[Mrows*Dd];
__device__ __align__(256) __half g_f[Mrows*FFd];
__device__ __align__(256) __half g_oH[Mrows*Dd];
__device__ __align__(256) __half g_q[Mrows*Dd];
__device__ __align__(256) __half g_k[Mrows*Dd];
__device__ __align__(256) __half g_v[Mrows*Dd];

// ---------------- PTX helpers (all legal on plain sm_103) ---------------------
__device__ __forceinline__ uint32_t smem_u32(const void* p) {
    uint32_t a;
    asm("{ .reg .u64 t; cvta.to.shared.u64 t, %1; cvt.u32.u64 %0, t; }" : "=r"(a) : "l"(p));
    return a;
}
__device__ __forceinline__ void cp16(uint32_t dst, const void* src) {
    asm volatile("cp.async.cg.shared.global [%0], [%1], 16;" :: "r"(dst), "l"(src) : "memory");
}
__device__ __forceinline__ void ldsm4(uint32_t* r, uint32_t addr) {
    asm volatile("ldmatrix.sync.aligned.m8n8.x4.shared.b16 {%0,%1,%2,%3}, [%4];"
                 : "=r"(r[0]), "=r"(r[1]), "=r"(r[2]), "=r"(r[3]) : "r"(addr));
}
__device__ __forceinline__ void ldsm4t(uint32_t* r, uint32_t addr) {
    asm volatile("ldmatrix.sync.aligned.m8n8.x4.trans.shared.b16 {%0,%1,%2,%3}, [%4];"
                 : "=r"(r[0]), "=r"(r[1]), "=r"(r[2]), "=r"(r[3]) : "r"(addr));
}
__device__ __forceinline__ void mma_f16(float* c, const uint32_t* a, uint32_t b0, uint32_t b1) {
    asm volatile(
        "mma.sync.aligned.m16n8k16.row.col.f32.f16.f16.f32 "
        "{%0,%1,%2,%3}, {%4,%5,%6,%7}, {%8,%9}, {%0,%1,%2,%3};"
        : "+f"(c[0]), "+f"(c[1]), "+f"(c[2]), "+f"(c[3])
        : "r"(a[0]), "r"(a[1]), "r"(a[2]), "r"(a[3]), "r"(b0), "r"(b1));
}
__device__ __forceinline__ uint32_t f2h2(float lo, float hi) {
    __half2 t = __floats2half2_rn(lo, hi);
    return *reinterpret_cast<uint32_t*>(&t);
}

// ---------------- fp32 -> fp16 convert (weights) ------------------------------
__global__ void conv_kernel(const float* __restrict__ in, __half* __restrict__ outp) {
    const int idx = blockIdx.x * 256 + threadIdx.x;    // float4 index
    float4 v = ((const float4*)in)[idx];
    ((uint32_t*)outp)[2*idx]   = f2h2(v.x, v.y);
    ((uint32_t*)outp)[2*idx+1] = f2h2(v.z, v.w);
}

// ---------------- LayerNorm over (L,D) jointly per batch ---------------------
__global__ void ln_partial(const float* __restrict__ x) {
    const int b = blockIdx.y;
    const int tid = threadIdx.x;
    const int chunk4 = (LD / NPART) / 4;
    const float4* xp = (const float4*)(x + (size_t)b * LD) + (size_t)blockIdx.x * chunk4;
    float s = 0.f, s2 = 0.f;
    for (int i = tid; i < chunk4; i += 256) {
        float4 v = xp[i];
        s  += v.x + v.y + v.z + v.w;
        s2 += v.x*v.x + v.y*v.y + v.z*v.z + v.w*v.w;
    }
    __shared__ float sh[2][256];
    sh[0][tid] = s; sh[1][tid] = s2;
    __syncthreads();
    for (int st = 128; st > 0; st >>= 1) {
        if (tid < st) { sh[0][tid] += sh[0][tid+st]; sh[1][tid] += sh[1][tid+st]; }
        __syncthreads();
    }
    if (tid == 0) {
        g_part[(b*NPART + blockIdx.x)*2 + 0] = sh[0][0];
        g_part[(b*NPART + blockIdx.x)*2 + 1] = sh[1][0];
    }
}

__global__ void ln_final() {
    const int b = blockIdx.x, t = threadIdx.x;   // 32 threads
    float s  = g_part[(b*NPART + t)*2 + 0] + g_part[(b*NPART + t + 32)*2 + 0];
    float s2 = g_part[(b*NPART + t)*2 + 1] + g_part[(b*NPART + t + 32)*2 + 1];
    for (int o = 16; o; o >>= 1) {
        s  += __shfl_xor_sync(0xffffffffu, s,  o);
        s2 += __shfl_xor_sync(0xffffffffu, s2, o);
    }
    if (t == 0) {
        float mu  = s / (float)LD;
        float var = s2 / (float)LD - mu*mu;
        g_stats[b*2 + 0] = mu;
        g_stats[b*2 + 1] = rsqrtf(var + 1e-5f);
    }
}

// normalize, emit single fp16
__global__ void ln_apply_h(const float* __restrict__ in, __half* __restrict__ outp) {
    const int idx = blockIdx.x * blockDim.x + threadIdx.x;   // float4 index
    const int b = idx / (LD/4);
    const float mu = g_stats[b*2 + 0], rs = g_stats[b*2 + 1];
    float4 v = ((const float4*)in)[idx];
    ((uint32_t*)outp)[2*idx]   = f2h2((v.x - mu)*rs, (v.y - mu)*rs);
    ((uint32_t*)outp)[2*idx+1] = f2h2((v.z - mu)*rs, (v.w - mu)*rs);
}

// ---------------- mma.sync fp16 GEMM ------------------------------------------
// C[M,N] = A[M,K] @ W[N,K]^T, fp32 accum, single-term fp16.
// 128x128 CTA tile, BK=32, 3-stage cp.async pipeline.
// Per stage 2 tiles (A, W), each 128 rows x 32 fp16, row stride 80B.
#define TILE_B   10240              // 128 * 80
#define STAGE_B  (2*TILE_B)         // 20480
#define GEMM_SMEM (3*STAGE_B)       // 61440

// OUT: 0 = fp32 C, 1 = fp16 Ch
template<bool RELU, bool RESID, int OUT>
__global__ __launch_bounds__(256)
void gemm_mma(const __half* __restrict__ A, const __half* __restrict__ W,
              const float* __restrict__ bias, const float* __restrict__ R,
              float* __restrict__ C, __half* __restrict__ Ch,
              int Ndim, int Kdim)
{
    extern __shared__ char smem[];
    const uint32_t sb = smem_u32(smem);
    const int tid  = threadIdx.x;
    const int wid  = tid >> 5, lane = tid & 31;
    const int wm   = wid & 3;
    const int wn   = wid >> 2;
    const int bm   = blockIdx.y * 128, bn = blockIdx.x * 128;

    float acc[2][8][4];
    #pragma unroll
    for (int i = 0; i < 2; i++)
        #pragma unroll
        for (int j = 0; j < 8; j++)
            #pragma unroll
            for (int t = 0; t < 4; t++) acc[i][j][t] = 0.f;

    const int r0c = tid >> 2, c0c = tid & 3;
    const int r1c = (tid + 256) >> 2, c1c = tid & 3;

    auto load_stage = [&](int s, int k0) {
        const uint32_t st = sb + s * STAGE_B;
        cp16(st + 0*TILE_B + r0c*80 + c0c*16, A + (size_t)(bm + r0c)*Kdim + k0 + c0c*8);
        cp16(st + 0*TILE_B + r1c*80 + c1c*16, A + (size_t)(bm + r1c)*Kdim + k0 + c1c*8);
        cp16(st + 1*TILE_B + r0c*80 + c0c*16, W + (size_t)(bn + r0c)*Kdim + k0 + c0c*8);
        cp16(st + 1*TILE_B + r1c*80 + c1c*16, W + (size_t)(bn + r1c)*Kdim + k0 + c1c*8);
        asm volatile("cp.async.commit_group;" ::: "memory");
    };

    const int nk = Kdim >> 5;
    load_stage(0, 0);
    load_stage(1, 32);

    for (int kt = 0; kt < nk; kt++) {
        if (kt + 1 < nk) { asm volatile("cp.async.wait_group 1;" ::: "memory"); }
        else             { asm volatile("cp.async.wait_group 0;" ::: "memory"); }
        __syncthreads();
        if (kt + 2 < nk) load_stage((kt + 2) % 3, (kt + 2) << 5);

        const uint32_t st = sb + (kt % 3) * STAGE_B;
        #pragma unroll
        for (int ks = 0; ks < 2; ks++) {
            const uint32_t koff = ks*32 + ((lane >> 4) & 1)*16;
            uint32_t a[2][4];
            #pragma unroll
            for (int mt = 0; mt < 2; mt++)
                ldsm4(a[mt], st + (wm*32 + mt*16 + (lane & 15))*80 + koff);
            #pragma unroll
            for (int g = 0; g < 4; g++) {
                const uint32_t rb = st + TILE_B + (wn*64 + g*16 + (lane & 15))*80 + koff;
                uint32_t wv[4];
                ldsm4(wv, rb);
                #pragma unroll
                for (int mt = 0; mt < 2; mt++) {
                    mma_f16(acc[mt][2*g],   a[mt], wv[0], wv[2]);
                    mma_f16(acc[mt][2*g+1], a[mt], wv[1], wv[3]);
                }
            }
        }
    }

    // ---- epilogue ----
    #pragma unroll
    for (int mt = 0; mt < 2; mt++) {
        const int row0 = bm + wm*32 + mt*16 + (lane >> 2);
        #pragma unroll
        for (int nt = 0; nt < 8; nt++) {
            const int cc = bn + wn*64 + nt*8 + (lane & 3)*2;
            const float b0 = bias[cc], b1 = bias[cc+1];
            float v00 = acc[mt][nt][0] + b0, v01 = acc[mt][nt][1] + b1;
            float v10 = acc[mt][nt][2] + b0, v11 = acc[mt][nt][3] + b1;
            if (RESID) {
                v00 += R[(size_t)row0*Ndim + cc];     v01 += R[(size_t)row0*Ndim + cc + 1];
                v10 += R[(size_t)(row0+8)*Ndim + cc]; v11 += R[(size_t)(row0+8)*Ndim + cc + 1];
            }
            if (RELU) {
                v00 = fmaxf(v00, 0.f); v01 = fmaxf(v01, 0.f);
                v10 = fmaxf(v10, 0.f); v11 = fmaxf(v11, 0.f);
            }
            if (OUT == 0) {
                *(float2*)(C + (size_t)row0*Ndim + cc)     = {v00, v01};
                *(float2*)(C + (size_t)(row0+8)*Ndim + cc) = {v10, v11};
            } else {
                *(uint32_t*)(Ch + (size_t)row0*Ndim + cc)     = f2h2(v00, v01);
                *(uint32_t*)(Ch + (size_t)(row0+8)*Ndim + cc) = f2h2(v10, v11);
            }
        }
    }
}

// ---------------- MMA flash attention (single-term fp16) ----------------------
// Per CTA: one (b, h), 128 q rows. 8 warps x 16 q rows.
// KV streamed in 64-key chunks, 3-stage cp.async.
#define AST 144                      // smem row stride bytes (64 fp16 + 16B pad)
#define ATT_Q  0
#define ATT_S0 (128*AST)             // 18432
#define ATT_STAGE (2*64*AST)         // 18432 (K tile + V tile)
#define ATT_Vo (64*AST)
#define ATT_SMEM (ATT_S0 + 3*ATT_STAGE)   // 73728

__global__ __launch_bounds__(256)
void attn_mma(const __half* __restrict__ q_g, const __half* __restrict__ k_g,
              const __half* __restrict__ v_g, __half* __restrict__ o_g)
{
    extern __shared__ char smem[];
    const uint32_t sb = smem_u32(smem);
    const int tid = threadIdx.x, w = tid >> 5, lane = tid & 31;
    const int b = blockIdx.z, h = blockIdx.y, q0 = blockIdx.x * 128;
    const size_t tokbase = (size_t)(b*Ls + q0);
    const int coff = h * DHd;

    // load Q tile, 128 rows x 128B
    #pragma unroll
    for (int it = 0; it < 4; it++) {
        const int unit = tid + it*256;
        const int r = unit >> 3, c = unit & 7;
        cp16(sb + ATT_Q + r*AST + c*16, q_g + (tokbase + r)*Dd + coff + c*8);
    }
    asm volatile("cp.async.commit_group;" ::: "memory");

    auto load_kv = [&](int s, int t0) {
        const uint32_t st = sb + ATT_S0 + s*ATT_STAGE;
        const size_t kb = (size_t)(b*Ls + t0);
        #pragma unroll
        for (int it = 0; it < 2; it++) {
            const int unit = tid + it*256;
            const int r = unit >> 3, c = unit & 7;
            cp16(st + r*AST + c*16,          k_g + (kb + r)*Dd + coff + c*8);
            cp16(st + ATT_Vo + r*AST + c*16, v_g + (kb + r)*Dd + coff + c*8);
        }
        asm volatile("cp.async.commit_group;" ::: "memory");
    };

    load_kv(0, 0);
    load_kv(1, 64);
    asm volatile("cp.async.wait_group 1;" ::: "memory");   // Q + kv0 ready
    __syncthreads();

    // Q fragments in registers (A operand, m16 rows = w*16)
    uint32_t qf[4][4];
    #pragma unroll
    for (int kc = 0; kc < 4; kc++)
        ldsm4(qf[kc], sb + ATT_Q + (w*16 + (lane & 15))*AST + kc*32 + ((lane >> 4) & 1)*16);

    float oacc[8][4];
    #pragma unroll
    for (int g = 0; g < 8; g++)
        #pragma unroll
        for (int i = 0; i < 4; i++) oacc[g][i] = 0.f;
    float m0 = -1e30f, m1 = -1e30f, l0 = 0.f, l1 = 0.f;

    const int nt = Ls/64;
    for (int t = 0; t < nt; t++) {
        if (t > 0) {
            if (t + 1 < nt) { asm volatile("cp.async.wait_group 1;" ::: "memory"); }
            else            { asm volatile("cp.async.wait_group 0;" ::: "memory"); }
            __syncthreads();
        }
        if (t + 2 < nt) load_kv((t + 2) % 3, (t + 2) * 64);
        const uint32_t st = sb + ATT_S0 + (t % 3)*ATT_STAGE;

        // ---- S = Q @ K^T ----
        float sc[8][4];
        #pragma unroll
        for (int g = 0; g < 8; g++)
            #pragma unroll
            for (int i = 0; i < 4; i++) sc[g][i] = 0.f;
        #pragma unroll
        for (int ng = 0; ng < 4; ng++) {
            #pragma unroll
            for (int kc = 0; kc < 4; kc++) {
                uint32_t bh[4];
                ldsm4(bh, st + (ng*16 + (lane & 15))*AST + kc*32 + ((lane >> 4) & 1)*16);
                mma_f16(sc[2*ng],   qf[kc], bh[0], bh[2]);
                mma_f16(sc[2*ng+1], qf[kc], bh[1], bh[3]);
            }
        }

        // ---- online softmax (scale = 1/sqrt(H) = 0.25, faithful to source) ----
        float rm0 = -1e30f, rm1 = -1e30f;
        #pragma unroll
        for (int g = 0; g < 8; g++) {
            sc[g][0] *= 0.25f; sc[g][1] *= 0.25f; sc[g][2] *= 0.25f; sc[g][3] *= 0.25f;
            rm0 = fmaxf(rm0, fmaxf(sc[g][0], sc[g][1]));
            rm1 = fmaxf(rm1, fmaxf(sc[g][2], sc[g][3]));
        }
        rm0 = fmaxf(rm0, __shfl_xor_sync(0xffffffffu, rm0, 1));
        rm0 = fmaxf(rm0, __shfl_xor_sync(0xffffffffu, rm0, 2));
        rm1 = fmaxf(rm1, __shfl_xor_sync(0xffffffffu, rm1, 1));
        rm1 = fmaxf(rm1, __shfl_xor_sync(0xffffffffu, rm1, 2));
        const float nm0 = fmaxf(m0, rm0), nm1 = fmaxf(m1, rm1);
        const float c0 = __expf(m0 - nm0), c1 = __expf(m1 - nm1);
        m0 = nm0; m1 = nm1;

        float ls0 = 0.f, ls1 = 0.f;
        uint32_t pf[4][4];
        #pragma unroll
        for (int g = 0; g < 8; g++) {
            const float p0 = __expf(sc[g][0] - m0);
            const float p1 = __expf(sc[g][1] - m0);
            const float p2 = __expf(sc[g][2] - m1);
            const float p3 = __expf(sc[g][3] - m1);
            ls0 += p0 + p1; ls1 += p2 + p3;
            const uint32_t hp01 = f2h2(p0, p1), hp23 = f2h2(p2, p3);
            const int kc = g >> 1;
            if ((g & 1) == 0) { pf[kc][0] = hp01; pf[kc][1] = hp23; }
            else              { pf[kc][2] = hp01; pf[kc][3] = hp23; }
            oacc[g][0] *= c0; oacc[g][1] *= c0; oacc[g][2] *= c1; oacc[g][3] *= c1;
        }
        ls0 += __shfl_xor_sync(0xffffffffu, ls0, 1);
        ls0 += __shfl_xor_sync(0xffffffffu, ls0, 2);
        ls1 += __shfl_xor_sync(0xffffffffu, ls1, 1);
        ls1 += __shfl_xor_sync(0xffffffffu, ls1, 2);
        l0 = l0*c0 + ls0; l1 = l1*c1 + ls1;

        // ---- O += P @ V, V^T via ldmatrix.trans ----
        #pragma unroll
        for (int ng = 0; ng < 4; ng++) {
            #pragma unroll
            for (int kc = 0; kc < 4; kc++) {
                uint32_t vv[4];
                ldsm4t(vv, st + ATT_Vo + (kc*16 + (lane & 15))*AST + ng*32 + ((lane >> 4) & 1)*16);
                mma_f16(oacc[2*ng],   pf[kc], vv[0], vv[1]);
                mma_f16(oacc[2*ng+1], pf[kc], vv[2], vv[3]);
            }
        }
    }

    // ---- epilogue: normalize, fp16 out ----
    const float inv0 = 1.f / l0, inv1 = 1.f / l1;
    const size_t row0 = tokbase + w*16 + (lane >> 2);
    #pragma unroll
    for (int g = 0; g < 8; g++) {
        const int cc = coff + g*8 + (lane & 3)*2;
        *(uint32_t*)(o_g + row0*Dd + cc)     = f2h2(oacc[g][0]*inv0, oacc[g][1]*inv0);
        *(uint32_t*)(o_g + (row0+8)*Dd + cc) = f2h2(oacc[g][2]*inv1, oacc[g][3]*inv1);
    }
}

// ---------------- host orchestration ----------------------------------------
extern "C" void kernel_launch(void* const* d_in, const int* in_sizes, int n_in,
                              void* d_out, int out_size)
{
    (void)in_sizes; (void)n_in; (void)out_size;
    const float* x  = (const float*)d_in[0];
    const float* wq = (const float*)d_in[1];
    const float* bq = (const float*)d_in[2];
    const float* wk = (const float*)d_in[3];
    const float* bk = (const float*)d_in[4];
    const float* wv = (const float*)d_in[5];
    const float* bv = (const float*)d_in[6];
    const float* wo = (const float*)d_in[7];
    const float* bo = (const float*)d_in[8];
    const float* w1 = (const float*)d_in[9];
    const float* b1 = (const float*)d_in[10];
    const float* w2 = (const float*)d_in[11];
    const float* b2 = (const float*)d_in[12];
    float* out = (float*)d_out;

    float *r1;
    cudaGetSymbolAddress((void**)&r1, g_r1);

    __half *wqH,*wkH,*wvH,*woH,*w1H,*w2H, *hA,*yA,*fA,*oA,*qA,*kA,*vA;
    cudaGetSymbolAddress((void**)&wqH, g_wq);
    cudaGetSymbolAddress((void**)&wkH, g_wk);
    cudaGetSymbolAddress((void**)&wvH, g_wv);
    cudaGetSymbolAddress((void**)&woH, g_wo);
    cudaGetSymbolAddress((void**)&w1H, g_w1);
    cudaGetSymbolAddress((void**)&w2H, g_w2);
    cudaGetSymbolAddress((void**)&hA,  g_h);
    cudaGetSymbolAddress((void**)&yA,  g_y);
    cudaGetSymbolAddress((void**)&fA,  g_f);
    cudaGetSymbolAddress((void**)&oA,  g_oH);
    cudaGetSymbolAddress((void**)&qA,  g_q);
    cudaGetSymbolAddress((void**)&kA,  g_k);
    cudaGetSymbolAddress((void**)&vA,  g_v);

    cudaFuncSetAttribute(gemm_mma<false,false,1>, cudaFuncAttributeMaxDynamicSharedMemorySize, GEMM_SMEM);
    cudaFuncSetAttribute(gemm_mma<false,true, 0>, cudaFuncAttributeMaxDynamicSharedMemorySize, GEMM_SMEM);
    cudaFuncSetAttribute(gemm_mma<true, false,1>, cudaFuncAttributeMaxDynamicSharedMemorySize, GEMM_SMEM);
    cudaFuncSetAttribute(attn_mma, cudaFuncAttributeMaxDynamicSharedMemorySize, ATT_SMEM);

    const dim3 gProj(Dd/128, Mrows/128);     // (8, 32)
    const dim3 gFF1(FFd/128, Mrows/128);     // (32, 32)

    // weight converts (fp32 -> fp16)
    conv_kernel<<<(Dd*Dd)/1024, 256>>>(wq, wqH);
    conv_kernel<<<(Dd*Dd)/1024, 256>>>(wk, wkH);
    conv_kernel<<<(Dd*Dd)/1024, 256>>>(wv, wvH);
    conv_kernel<<<(Dd*Dd)/1024, 256>>>(wo, woH);
    conv_kernel<<<(FFd*Dd)/1024, 256>>>(w1, w1H);
    conv_kernel<<<(Dd*FFd)/1024, 256>>>(w2, w2H);

    // LN1 -> h (fp16)
    ln_partial<<<dim3(NPART, Bb), 256>>>(x);
    ln_final<<<Bb, 32>>>();
    ln_apply_h<<<(Mrows*Dd)/4/256, 256>>>(x, hA);

    // QKV projections (fp16 out)
    gemm_mma<false,false,1><<<gProj, 256, GEMM_SMEM>>>(hA, wqH, bq, nullptr, nullptr, qA, Dd, Dd);
    gemm_mma<false,false,1><<<gProj, 256, GEMM_SMEM>>>(hA, wkH, bk, nullptr, nullptr, kA, Dd, Dd);
    gemm_mma<false,false,1><<<gProj, 256, GEMM_SMEM>>>(hA, wvH, bv, nullptr, nullptr, vA, Dd, Dd);

    // attention (MMA) -> fp16 o
    attn_mma<<<dim3(Ls/128, Hh, Bb), 256, ATT_SMEM>>>(qA, kA, vA, oA);

    // out-proj + residual(x) -> fp32 r1
    gemm_mma<false,true,0><<<gProj, 256, GEMM_SMEM>>>(oA, woH, bo, x, r1, nullptr, Dd, Dd);

    // LN2 -> y (fp16)
    ln_partial<<<dim3(NPART, Bb), 256>>>(r1);
    ln_final<<<Bb, 32>>>();
    ln_apply_h<<<(Mrows*Dd)/4/256, 256>>>(r1, yA);

    // FFN1: relu, fp16 f
    gemm_mma<true,false,1><<<gFF1, 256, GEMM_SMEM>>>(yA, w1H, b1, nullptr, nullptr, fA, FFd, Dd);
    // FFN2: + residual(x), fp32 out
    gemm_mma<false,true,0><<<gProj, 256, GEMM_SMEM>>>(fA, w2H, b2, x, out, nullptr, Dd, FFd);
}